// round 1
// baseline (speedup 1.0000x reference)
#include <cuda_runtime.h>
#include <math.h>

// ---------------- problem constants ----------------
#define BATCH   128
#define NTOK    394        // 197 (p2r) + 197 (p1)
#define EMBD    256
#define NP      196        // patches per branch actually used
#define HEADS   2
#define DH      128
#define K1      768        // 16*16*3
#define K2      192        // 8*8*3
#define ROWS_E  (BATCH*NP)         // 25088
#define ROWS_T  (BATCH*NTOK)       // 50432
#define ATTN_N  394
#define ATTN_SZ (ATTN_N*ATTN_N)    // 155236

// ---------------- scratch (device globals; no allocation allowed) ----------------
__device__ float g_patch1[(size_t)ROWS_E * K1];   // 77 MB
__device__ float g_patch2[(size_t)ROWS_E * K2];   // 19 MB
__device__ float g_emb1 [(size_t)ROWS_E * EMBD];
__device__ float g_emb2 [(size_t)ROWS_E * EMBD];
__device__ float g_z    [(size_t)ROWS_T * EMBD];
__device__ float g_h    [(size_t)ROWS_T * EMBD];
__device__ float g_q    [(size_t)ROWS_T * EMBD];
__device__ float g_k    [(size_t)ROWS_T * EMBD];
__device__ float g_v    [(size_t)ROWS_T * EMBD];
__device__ float g_o    [(size_t)ROWS_T * EMBD];
__device__ float g_op   [(size_t)ROWS_T * EMBD];
__device__ float g_attn [(size_t)BATCH * HEADS * ATTN_SZ]; // 159 MB

// ---------------- block reductions ----------------
__device__ __forceinline__ float block_sum_256(float v, float* sh) {
    #pragma unroll
    for (int o = 16; o > 0; o >>= 1) v += __shfl_xor_sync(0xffffffffu, v, o);
    __syncthreads();
    if ((threadIdx.x & 31) == 0) sh[threadIdx.x >> 5] = v;
    __syncthreads();
    float r = 0.f;
    #pragma unroll
    for (int i = 0; i < 8; i++) r += sh[i];
    return r;
}

__device__ __forceinline__ float block_sum_128(float v, float* sh) {
    #pragma unroll
    for (int o = 16; o > 0; o >>= 1) v += __shfl_xor_sync(0xffffffffu, v, o);
    __syncthreads();
    if ((threadIdx.x & 31) == 0) sh[threadIdx.x >> 5] = v;
    __syncthreads();
    return sh[0] + sh[1] + sh[2] + sh[3];
}

__device__ __forceinline__ float block_max_128(float v, float* sh) {
    #pragma unroll
    for (int o = 16; o > 0; o >>= 1) v = fmaxf(v, __shfl_xor_sync(0xffffffffu, v, o));
    __syncthreads();
    if ((threadIdx.x & 31) == 0) sh[threadIdx.x >> 5] = v;
    __syncthreads();
    return fmaxf(fmaxf(sh[0], sh[1]), fmaxf(sh[2], sh[3]));
}

// ---------------- im2row ----------------
// patch1: p=16, grid 14x14, f = pr*48 + pc*3 + c
__global__ void im2row1_kernel(const float* __restrict__ x) {
    int idx = blockIdx.x * 256 + threadIdx.x;           // < ROWS_E*K1
    int f = idx % K1;
    int r = idx / K1;
    int b = r / NP, i = r % NP;
    int hi = i / 14, wi = i % 14;
    int pr = f / 48; int rem = f % 48; int pc = rem / 3; int c = rem % 3;
    g_patch1[idx] = x[(((size_t)b * 3 + c) * 224 + (hi * 16 + pr)) * 224 + (wi * 16 + pc)];
}

// patch2 (gathered): row j holds patch m = 4j+3 of the 28x28 grid; p=8, f = pr*24+pc*3+c
__global__ void im2row2_kernel(const float* __restrict__ x) {
    int idx = blockIdx.x * 256 + threadIdx.x;           // < ROWS_E*K2
    int f = idx % K2;
    int r = idx / K2;
    int b = r / NP, j = r % NP;
    int m = 4 * j + 3;
    int hi = m / 28, wi = m % 28;
    int pr = f / 24; int rem = f % 24; int pc = rem / 3; int c = rem % 3;
    g_patch2[idx] = x[(((size_t)b * 3 + c) * 224 + (hi * 8 + pr)) * 224 + (wi * 8 + pc)];
}

// ---------------- generic tiled GEMM (batched, optional B^T, optional bias) ----------------
// C[M,N] = A[M,K] * op(B) + bias, per-z offsets: base + (z/nh)*s?b + (z%nh)*s?h
template <bool TRANSB>
__global__ void gemm_kernel(const float* __restrict__ A, const float* __restrict__ B,
                            const float* __restrict__ bias, float* __restrict__ C,
                            int M, int N, int K, int lda, int ldb, int ldc,
                            int nh,
                            long long sAb, long long sAh,
                            long long sBb, long long sBh,
                            long long sCb, long long sCh) {
    const int BM = 64, BN = 64, BK = 16;
    __shared__ float As[BK][BM + 1];
    __shared__ float Bs[BK][BN + 1];

    int z = blockIdx.z;
    int zb = z / nh, zh = z % nh;
    A += zb * sAb + zh * sAh;
    B += zb * sBb + zh * sBh;
    C += zb * sCb + zh * sCh;

    int m0 = blockIdx.y * BM, n0 = blockIdx.x * BN;
    int tid = threadIdx.x;
    int ty = tid >> 4, tx = tid & 15;

    float acc[4][4] = {};

    for (int k0 = 0; k0 < K; k0 += BK) {
        #pragma unroll
        for (int i = 0; i < 4; i++) {
            int idx = i * 256 + tid;
            int m = idx >> 4;
            int kk = idx & 15;
            float val = 0.f;
            int gm = m0 + m, gk = k0 + kk;
            if (gm < M && gk < K) val = A[(long long)gm * lda + gk];
            As[kk][m] = val;
        }
        #pragma unroll
        for (int i = 0; i < 4; i++) {
            int idx = i * 256 + tid;
            if (!TRANSB) {
                int kk = idx >> 6;
                int n = idx & 63;
                float val = 0.f;
                int gk = k0 + kk, gn = n0 + n;
                if (gk < K && gn < N) val = B[(long long)gk * ldb + gn];
                Bs[kk][n] = val;
            } else {
                int n = idx >> 4;
                int kk = idx & 15;
                float val = 0.f;
                int gk = k0 + kk, gn = n0 + n;
                if (gn < N && gk < K) val = B[(long long)gn * ldb + gk];
                Bs[kk][n] = val;
            }
        }
        __syncthreads();
        #pragma unroll
        for (int kk = 0; kk < BK; kk++) {
            float a[4], b[4];
            #pragma unroll
            for (int i = 0; i < 4; i++) a[i] = As[kk][ty * 4 + i];
            #pragma unroll
            for (int j = 0; j < 4; j++) b[j] = Bs[kk][tx * 4 + j];
            #pragma unroll
            for (int i = 0; i < 4; i++)
                #pragma unroll
                for (int j = 0; j < 4; j++)
                    acc[i][j] += a[i] * b[j];
        }
        __syncthreads();
    }

    #pragma unroll
    for (int i = 0; i < 4; i++) {
        int gm = m0 + ty * 4 + i;
        if (gm >= M) continue;
        #pragma unroll
        for (int j = 0; j < 4; j++) {
            int gn = n0 + tx * 4 + j;
            if (gn >= N) continue;
            float val = acc[i][j];
            if (bias) val += bias[gn];
            C[(long long)gm * ldc + gn] = val;
        }
    }
}

// ---------------- assemble z = concat(p2r, p1) ----------------
__global__ void assemble_kernel(const float* __restrict__ b1, const float* __restrict__ cls1,
                                const float* __restrict__ b2, const float* __restrict__ cls2) {
    int n = blockIdx.x;     // 0..393
    int b = blockIdx.y;     // 0..127
    int c = threadIdx.x;    // 0..255
    float val;
    if (n == 0)            val = cls2[c];
    else if (n <= NP)      val = g_emb2[((size_t)(b * NP + (n - 1))) * EMBD + c] + b2[c];
    else if (n == NP + 1)  val = cls1[c];
    else                   val = g_emb1[((size_t)(b * NP + (n - NP - 2))) * EMBD + c] + b1[c];
    g_z[((size_t)b * NTOK + n) * EMBD + c] = val;
}

// ---------------- layer norms ----------------
__global__ void ln_kernel(const float* __restrict__ in, const float* __restrict__ gw,
                          const float* __restrict__ bw, float* __restrict__ out) {
    __shared__ float sh[8];
    long long row = blockIdx.x;
    int c = threadIdx.x;
    float v = in[row * EMBD + c];
    float mean = block_sum_256(v, sh) * (1.f / EMBD);
    float d = v - mean;
    float var = block_sum_256(d * d, sh) * (1.f / EMBD);
    out[row * EMBD + c] = d * rsqrtf(var + 1e-5f) * gw[c] + bw[c];
}

// z += LN(op)
__global__ void ln_res_kernel(const float* __restrict__ gw, const float* __restrict__ bw) {
    __shared__ float sh[8];
    long long row = blockIdx.x;
    int c = threadIdx.x;
    float v = g_op[row * EMBD + c];
    float mean = block_sum_256(v, sh) * (1.f / EMBD);
    float d = v - mean;
    float var = block_sum_256(d * d, sh) * (1.f / EMBD);
    g_z[row * EMBD + c] += d * rsqrtf(var + 1e-5f) * gw[c] + bw[c];
}

// ---------------- softmax(rows of attn) / 16 ----------------
__global__ void softmax_kernel() {
    __shared__ float sh[4];
    long long row = blockIdx.x;   // BATCH*HEADS*394
    float* p = g_attn + row * ATTN_N;
    int t = threadIdx.x;          // 128
    float mx = -1e30f;
    for (int j = t; j < ATTN_N; j += 128) mx = fmaxf(mx, p[j]);
    mx = block_max_128(mx, sh);
    float s = 0.f;
    for (int j = t; j < ATTN_N; j += 128) {
        float e = __expf(p[j] - mx);
        p[j] = e;
        s += e;
    }
    s = block_sum_128(s, sh);
    float inv = 1.f / (s * 16.f);   // softmax then /sqrt(256)
    for (int j = t; j < ATTN_N; j += 128) p[j] *= inv;
}

// ---------------- head: pool -> LN -> classifier -> log_softmax ----------------
__global__ void head_kernel(const float* __restrict__ lg, const float* __restrict__ lb,
                            const float* __restrict__ Wc, const float* __restrict__ bc,
                            float* __restrict__ out) {
    __shared__ float sh[8];
    int b = blockIdx.x;
    int c = threadIdx.x;
    const float* zb = g_z + (size_t)b * NTOK * EMBD;
    float s = 0.f;
    for (int n = 0; n < NTOK; n++) s += zb[(size_t)n * EMBD + c];
    float pooled = s * (1.f / NTOK);
    float mean = block_sum_256(pooled, sh) * (1.f / EMBD);
    float d = pooled - mean;
    float var = block_sum_256(d * d, sh) * (1.f / EMBD);
    float ln = d * rsqrtf(var + 1e-5f) * lg[c] + lb[c];
    float l0 = block_sum_256(ln * Wc[c * 2 + 0], sh);
    float l1 = block_sum_256(ln * Wc[c * 2 + 1], sh);
    if (c == 0) {
        l0 += bc[0];
        l1 += bc[1];
        float mx = fmaxf(l0, l1);
        float lse = mx + logf(expf(l0 - mx) + expf(l1 - mx));
        out[b * 2 + 0] = l0 - lse;
        out[b * 2 + 1] = l1 - lse;
    }
}

// ---------------- launch ----------------
extern "C" void kernel_launch(void* const* d_in, const int* in_sizes, int n_in,
                              void* d_out, int out_size) {
    const float* x    = (const float*)d_in[0];
    const float* W1   = (const float*)d_in[1];
    const float* b1   = (const float*)d_in[2];
    const float* cls1 = (const float*)d_in[3];
    const float* W2   = (const float*)d_in[4];
    const float* b2   = (const float*)d_in[5];
    const float* cls2 = (const float*)d_in[6];
    const float* ln1g = (const float*)d_in[7];
    const float* ln1b = (const float*)d_in[8];
    const float* Wq   = (const float*)d_in[9];
    const float* bq   = (const float*)d_in[10];
    const float* Wk   = (const float*)d_in[11];
    const float* bk   = (const float*)d_in[12];
    const float* Wv   = (const float*)d_in[13];
    const float* bv   = (const float*)d_in[14];
    const float* Wp   = (const float*)d_in[15];
    const float* bp   = (const float*)d_in[16];
    const float* ln2g = (const float*)d_in[17];
    const float* ln2b = (const float*)d_in[18];
    const float* lncg = (const float*)d_in[19];
    const float* lncb = (const float*)d_in[20];
    const float* Wc   = (const float*)d_in[21];
    const float* bc   = (const float*)d_in[22];
    float* out = (float*)d_out;

    float *p1, *p2, *e1, *e2, *zp, *hp, *qp, *kp, *vp, *op_, *oo, *attn;
    cudaGetSymbolAddress((void**)&p1, g_patch1);
    cudaGetSymbolAddress((void**)&p2, g_patch2);
    cudaGetSymbolAddress((void**)&e1, g_emb1);
    cudaGetSymbolAddress((void**)&e2, g_emb2);
    cudaGetSymbolAddress((void**)&zp, g_z);
    cudaGetSymbolAddress((void**)&hp, g_h);
    cudaGetSymbolAddress((void**)&qp, g_q);
    cudaGetSymbolAddress((void**)&kp, g_k);
    cudaGetSymbolAddress((void**)&vp, g_v);
    cudaGetSymbolAddress((void**)&oo, g_o);
    cudaGetSymbolAddress((void**)&op_, g_op);
    cudaGetSymbolAddress((void**)&attn, g_attn);

    // 1) im2row both branches
    im2row1_kernel<<<(ROWS_E * K1) / 256, 256>>>(x);
    im2row2_kernel<<<(ROWS_E * K2) / 256, 256>>>(x);

    // 2) patch-embed GEMMs (bias applied during assemble)
    gemm_kernel<false><<<dim3(EMBD / 64, ROWS_E / 64, 1), 256>>>(
        p1, W1, nullptr, e1, ROWS_E, EMBD, K1, K1, EMBD, EMBD,
        1, 0, 0, 0, 0, 0, 0);
    gemm_kernel<false><<<dim3(EMBD / 64, ROWS_E / 64, 1), 256>>>(
        p2, W2, nullptr, e2, ROWS_E, EMBD, K2, K2, EMBD, EMBD,
        1, 0, 0, 0, 0, 0, 0);

    // 3) assemble z
    assemble_kernel<<<dim3(NTOK, BATCH), 256>>>(b1, cls1, b2, cls2);

    // 4) LN1: h = LN(z)
    ln_kernel<<<ROWS_T, 256>>>(zp, ln1g, ln1b, hp);

    // 5) QKV projections
    gemm_kernel<false><<<dim3(EMBD / 64, ROWS_T / 64, 1), 256>>>(
        hp, Wq, bq, qp, ROWS_T, EMBD, EMBD, EMBD, EMBD, EMBD, 1, 0, 0, 0, 0, 0, 0);
    gemm_kernel<false><<<dim3(EMBD / 64, ROWS_T / 64, 1), 256>>>(
        hp, Wk, bk, kp, ROWS_T, EMBD, EMBD, EMBD, EMBD, EMBD, 1, 0, 0, 0, 0, 0, 0);
    gemm_kernel<false><<<dim3(EMBD / 64, ROWS_T / 64, 1), 256>>>(
        hp, Wv, bv, vp, ROWS_T, EMBD, EMBD, EMBD, EMBD, EMBD, 1, 0, 0, 0, 0, 0, 0);

    // 6) attention scores: attn[b,h] = Q_bh (394x128) @ K_bh^T
    gemm_kernel<true><<<dim3(7, 7, BATCH * HEADS), 256>>>(
        qp, kp, nullptr, attn, ATTN_N, ATTN_N, DH, EMBD, EMBD, ATTN_N,
        HEADS,
        (long long)NTOK * EMBD, DH,
        (long long)NTOK * EMBD, DH,
        (long long)HEADS * ATTN_SZ, (long long)ATTN_SZ);

    // 7) softmax rows (then /16)
    softmax_kernel<<<BATCH * HEADS * ATTN_N, 128>>>();

    // 8) o[b,h] = attn_bh (394x394) @ V_bh (394x128)
    gemm_kernel<false><<<dim3(2, 7, BATCH * HEADS), 256>>>(
        attn, vp, nullptr, oo, ATTN_N, DH, ATTN_N, ATTN_N, EMBD, EMBD,
        HEADS,
        (long long)HEADS * ATTN_SZ, (long long)ATTN_SZ,
        (long long)NTOK * EMBD, DH,
        (long long)NTOK * EMBD, DH);

    // 9) output projection
    gemm_kernel<false><<<dim3(EMBD / 64, ROWS_T / 64, 1), 256>>>(
        oo, Wp, bp, op_, ROWS_T, EMBD, EMBD, EMBD, EMBD, EMBD, 1, 0, 0, 0, 0, 0, 0);

    // 10) z += LN2(op)
    ln_res_kernel<<<ROWS_T, 256>>>(ln2g, ln2b);

    // 11) pool + LN + classifier + log_softmax
    head_kernel<<<BATCH, 256>>>(lncg, lncb, Wc, bc, out);
}

// round 4
// speedup vs baseline: 1.2850x; 1.2850x over previous
#include <cuda_runtime.h>
#include <math.h>

// ---------------- problem constants ----------------
#define BATCH   128
#define NTOK    394
#define EMBD    256
#define NP      196
#define HEADS   2
#define DH      128
#define K1      768
#define K2      192
#define ROWS_E  (BATCH*NP)         // 25088
#define ROWS_T  (BATCH*NTOK)       // 50432

// ---------------- scratch ----------------
__device__ float g_patch1[(size_t)ROWS_E * K1];
__device__ float g_patch2[(size_t)ROWS_E * K2];
__device__ float g_emb1 [(size_t)ROWS_E * EMBD];
__device__ float g_emb2 [(size_t)ROWS_E * EMBD];
__device__ float g_z    [(size_t)ROWS_T * EMBD];
__device__ float g_h    [(size_t)ROWS_T * EMBD];
__device__ float g_qkv  [(size_t)ROWS_T * 768];
__device__ float g_o    [(size_t)ROWS_T * EMBD];
__device__ float g_op   [(size_t)ROWS_T * EMBD];
__device__ float g_Wqkv [(size_t)EMBD * 768];
__device__ float g_bqkv [768];

// ---------------- block reductions ----------------
__device__ __forceinline__ float block_sum_256(float v, float* sh) {
    #pragma unroll
    for (int o = 16; o > 0; o >>= 1) v += __shfl_xor_sync(0xffffffffu, v, o);
    __syncthreads();
    if ((threadIdx.x & 31) == 0) sh[threadIdx.x >> 5] = v;
    __syncthreads();
    float r = 0.f;
    #pragma unroll
    for (int i = 0; i < 8; i++) r += sh[i];
    return r;
}

// ---------------- im2row ----------------
__global__ void im2row1_kernel(const float* __restrict__ x) {
    int idx = blockIdx.x * 256 + threadIdx.x;
    int f = idx % K1;
    int r = idx / K1;
    int b = r / NP, i = r % NP;
    int hi = i / 14, wi = i % 14;
    int pr = f / 48; int rem = f % 48; int pc = rem / 3; int c = rem % 3;
    g_patch1[idx] = x[(((size_t)b * 3 + c) * 224 + (hi * 16 + pr)) * 224 + (wi * 16 + pc)];
}

__global__ void im2row2_kernel(const float* __restrict__ x) {
    int idx = blockIdx.x * 256 + threadIdx.x;
    int f = idx % K2;
    int r = idx / K2;
    int b = r / NP, j = r % NP;
    int m = 4 * j + 3;
    int hi = m / 28, wi = m % 28;
    int pr = f / 24; int rem = f % 24; int pc = rem / 3; int c = rem % 3;
    g_patch2[idx] = x[(((size_t)b * 3 + c) * 224 + (hi * 8 + pr)) * 224 + (wi * 8 + pc)];
}

// ---------------- QKV weight concat ----------------
__global__ void concat_qkvw(const float* __restrict__ Wq, const float* __restrict__ Wk,
                            const float* __restrict__ Wv, const float* __restrict__ bq,
                            const float* __restrict__ bk, const float* __restrict__ bv) {
    int idx = blockIdx.x * 256 + threadIdx.x;   // 256*768
    int r = idx / 768, c = idx % 768;
    const float* src = (c < 256) ? Wq : ((c < 512) ? Wk : Wv);
    int cc = c & 255;
    g_Wqkv[idx] = src[r * 256 + cc];
    if (r == 0) g_bqkv[c] = ((c < 256) ? bq : ((c < 512) ? bk : bv))[cc];
}

// ---------------- 128x128x16 double-buffered GEMM, 8x8 per thread ----------------
// C[M,N] = A[M,K] @ B[K,N] (+bias). Requires M%128==0, N%128==0, K%16==0.
__global__ __launch_bounds__(256, 2)
void gemm128(const float* __restrict__ A, const float* __restrict__ B,
             const float* __restrict__ bias, float* __restrict__ C,
             int M, int N, int K) {
    __shared__ float As[2][128][20];
    __shared__ float Bs[2][16][128];

    int tid = threadIdx.x;
    int tx = tid & 15, ty = tid >> 4;
    int m0 = blockIdx.y * 128, n0 = blockIdx.x * 128;

    const float* Ab = A + (size_t)m0 * K;
    const float* Bb = B + n0;

    int am = tid >> 2;          // 0..63
    int ak = (tid & 3) * 4;     // 0,4,8,12
    int bk = tid >> 5;          // 0..7
    int bn = (tid & 31) * 4;    // 0..124

    float4 rA0, rA1, rB0, rB1;
    rA0 = *(const float4*)(Ab + (size_t)am * K + ak);
    rA1 = *(const float4*)(Ab + (size_t)(am + 64) * K + ak);
    rB0 = *(const float4*)(Bb + (size_t)bk * N + bn);
    rB1 = *(const float4*)(Bb + (size_t)(bk + 8) * N + bn);
    *(float4*)&As[0][am][ak]      = rA0;
    *(float4*)&As[0][am + 64][ak] = rA1;
    *(float4*)&Bs[0][bk][bn]      = rB0;
    *(float4*)&Bs[0][bk + 8][bn]  = rB1;
    __syncthreads();

    float acc[8][8] = {};
    int kt = K >> 4;
    for (int t = 0; t < kt; t++) {
        int cur = t & 1;
        if (t + 1 < kt) {
            const float* Ap = Ab + (t + 1) * 16;
            rA0 = *(const float4*)(Ap + (size_t)am * K + ak);
            rA1 = *(const float4*)(Ap + (size_t)(am + 64) * K + ak);
            const float* Bp = Bb + (size_t)(t + 1) * 16 * N;
            rB0 = *(const float4*)(Bp + (size_t)bk * N + bn);
            rB1 = *(const float4*)(Bp + (size_t)(bk + 8) * N + bn);
        }
        #pragma unroll
        for (int kk = 0; kk < 16; kk++) {
            float a[8], b[8];
            #pragma unroll
            for (int i = 0; i < 4; i++) {
                a[i]     = As[cur][ty * 4 + i][kk];
                a[4 + i] = As[cur][64 + ty * 4 + i][kk];
            }
            float4 b0 = *(float4*)&Bs[cur][kk][tx * 4];
            float4 b1 = *(float4*)&Bs[cur][kk][64 + tx * 4];
            b[0] = b0.x; b[1] = b0.y; b[2] = b0.z; b[3] = b0.w;
            b[4] = b1.x; b[5] = b1.y; b[6] = b1.z; b[7] = b1.w;
            #pragma unroll
            for (int i = 0; i < 8; i++)
                #pragma unroll
                for (int j = 0; j < 8; j++)
                    acc[i][j] += a[i] * b[j];
        }
        if (t + 1 < kt) {
            int nxt = cur ^ 1;
            *(float4*)&As[nxt][am][ak]      = rA0;
            *(float4*)&As[nxt][am + 64][ak] = rA1;
            *(float4*)&Bs[nxt][bk][bn]      = rB0;
            *(float4*)&Bs[nxt][bk + 8][bn]  = rB1;
        }
        __syncthreads();
    }

    #pragma unroll
    for (int ih = 0; ih < 2; ih++) {
        #pragma unroll
        for (int i = 0; i < 4; i++) {
            int row = m0 + ih * 64 + ty * 4 + i;
            float* Crow = C + (size_t)row * N + n0;
            #pragma unroll
            for (int jh = 0; jh < 2; jh++) {
                int col = jh * 64 + tx * 4;
                float4 v;
                v.x = acc[ih * 4 + i][jh * 4 + 0];
                v.y = acc[ih * 4 + i][jh * 4 + 1];
                v.z = acc[ih * 4 + i][jh * 4 + 2];
                v.w = acc[ih * 4 + i][jh * 4 + 3];
                if (bias) {
                    v.x += bias[n0 + col + 0];
                    v.y += bias[n0 + col + 1];
                    v.z += bias[n0 + col + 2];
                    v.w += bias[n0 + col + 3];
                }
                *(float4*)(Crow + col) = v;
            }
        }
    }
}

// ---------------- assemble z = concat(p2r, p1) ----------------
__global__ void assemble_kernel(const float* __restrict__ b1, const float* __restrict__ cls1,
                                const float* __restrict__ b2, const float* __restrict__ cls2) {
    int n = blockIdx.x;
    int b = blockIdx.y;
    int c = threadIdx.x;
    float val;
    if (n == 0)            val = cls2[c];
    else if (n <= NP)      val = g_emb2[((size_t)(b * NP + (n - 1))) * EMBD + c] + b2[c];
    else if (n == NP + 1)  val = cls1[c];
    else                   val = g_emb1[((size_t)(b * NP + (n - NP - 2))) * EMBD + c] + b1[c];
    g_z[((size_t)b * NTOK + n) * EMBD + c] = val;
}

// ---------------- layer norms ----------------
__global__ void ln_kernel(const float* __restrict__ in, const float* __restrict__ gw,
                          const float* __restrict__ bw, float* __restrict__ out) {
    __shared__ float sh[8];
    long long row = blockIdx.x;
    int c = threadIdx.x;
    float v = in[row * EMBD + c];
    float mean = block_sum_256(v, sh) * (1.f / EMBD);
    float d = v - mean;
    float var = block_sum_256(d * d, sh) * (1.f / EMBD);
    out[row * EMBD + c] = d * rsqrtf(var + 1e-5f) * gw[c] + bw[c];
}

__global__ void ln_res_kernel(const float* __restrict__ gw, const float* __restrict__ bw) {
    __shared__ float sh[8];
    long long row = blockIdx.x;
    int c = threadIdx.x;
    float v = g_op[row * EMBD + c];
    float mean = block_sum_256(v, sh) * (1.f / EMBD);
    float d = v - mean;
    float var = block_sum_256(d * d, sh) * (1.f / EMBD);
    g_z[row * EMBD + c] += d * rsqrtf(var + 1e-5f) * gw[c] + bw[c];
}

// ---------------- fused flash attention ----------------
// grid (7, BATCH*HEADS), block 256. BM=64 q rows, BN=64 k cols, D=128.
// smem (dynamic): Qt[128][68], Kt[128][68], Vs[64][128], Pt[64][68]
#define FA_SMEM ((128*68 + 128*68 + 64*128 + 64*68) * 4)

__global__ __launch_bounds__(256, 1)
void flash_attn_kernel() {
    extern __shared__ float fsm[];
    float* Qt = fsm;                    // [d][m] pitch 68
    float* Kt = Qt + 128 * 68;          // [d][n] pitch 68
    float* Vs = Kt + 128 * 68;          // [n][d] pitch 128
    float* Pt = Vs + 64 * 128;          // [n][m] pitch 68

    int tid = threadIdx.x;
    int tx = tid & 15, ty = tid >> 4;
    int m0 = blockIdx.x * 64;
    int bh = blockIdx.y;
    int b = bh >> 1, h = bh & 1;

    const float* base = g_qkv + (size_t)b * NTOK * 768;
    const float* qb = base + h * DH;          // q cols
    const float* kb = base + 256 + h * DH;    // k cols
    const float* vb = base + 512 + h * DH;    // v cols

    // load Q tile transposed
    for (int i = tid; i < 64 * 32; i += 256) {
        int r = i >> 5, d4 = (i & 31) * 4;
        float4 v = make_float4(0.f, 0.f, 0.f, 0.f);
        if (m0 + r < NTOK) v = *(const float4*)(qb + (size_t)(m0 + r) * 768 + d4);
        Qt[(d4 + 0) * 68 + r] = v.x;
        Qt[(d4 + 1) * 68 + r] = v.y;
        Qt[(d4 + 2) * 68 + r] = v.z;
        Qt[(d4 + 3) * 68 + r] = v.w;
    }

    float o[4][8];
    #pragma unroll
    for (int i = 0; i < 4; i++)
        #pragma unroll
        for (int j = 0; j < 8; j++) o[i][j] = 0.f;
    float rm[4], rl[4];
    #pragma unroll
    for (int i = 0; i < 4; i++) { rm[i] = -1e30f; rl[i] = 0.f; }

    for (int nt = 0; nt < 7; nt++) {
        int n0c = nt * 64;
        // load K chunk transposed + V chunk
        for (int i = tid; i < 64 * 32; i += 256) {
            int r = i >> 5, d4 = (i & 31) * 4;
            float4 v = make_float4(0.f, 0.f, 0.f, 0.f);
            if (n0c + r < NTOK) v = *(const float4*)(kb + (size_t)(n0c + r) * 768 + d4);
            Kt[(d4 + 0) * 68 + r] = v.x;
            Kt[(d4 + 1) * 68 + r] = v.y;
            Kt[(d4 + 2) * 68 + r] = v.z;
            Kt[(d4 + 3) * 68 + r] = v.w;
            float4 w = make_float4(0.f, 0.f, 0.f, 0.f);
            if (n0c + r < NTOK) w = *(const float4*)(vb + (size_t)(n0c + r) * 768 + d4);
            *(float4*)&Vs[r * 128 + d4] = w;
        }
        __syncthreads();

        // S = Qtile @ Kchunk^T  (4x4 per thread)
        float s[4][4];
        #pragma unroll
        for (int i = 0; i < 4; i++)
            #pragma unroll
            for (int j = 0; j < 4; j++) s[i][j] = 0.f;
        for (int d = 0; d < 128; d++) {
            float4 a = *(float4*)&Qt[d * 68 + ty * 4];
            float4 bb = *(float4*)&Kt[d * 68 + tx * 4];
            float av[4] = {a.x, a.y, a.z, a.w};
            float bv_[4] = {bb.x, bb.y, bb.z, bb.w};
            #pragma unroll
            for (int i = 0; i < 4; i++)
                #pragma unroll
                for (int j = 0; j < 4; j++)
                    s[i][j] += av[i] * bv_[j];
        }
        // mask invalid cols
        #pragma unroll
        for (int j = 0; j < 4; j++)
            if (n0c + tx * 4 + j >= NTOK)
                #pragma unroll
                for (int i = 0; i < 4; i++) s[i][j] = -1e30f;

        // online softmax (16-lane groups share a row set)
        #pragma unroll
        for (int i = 0; i < 4; i++) {
            float cm = fmaxf(fmaxf(s[i][0], s[i][1]), fmaxf(s[i][2], s[i][3]));
            #pragma unroll
            for (int off = 8; off > 0; off >>= 1)
                cm = fmaxf(cm, __shfl_xor_sync(0xffffffffu, cm, off));
            float newm = fmaxf(rm[i], cm);
            float pscale = __expf(rm[i] - newm);
            rm[i] = newm;
            float rs = 0.f;
            #pragma unroll
            for (int j = 0; j < 4; j++) {
                s[i][j] = __expf(s[i][j] - newm);
                rs += s[i][j];
            }
            #pragma unroll
            for (int off = 8; off > 0; off >>= 1)
                rs += __shfl_xor_sync(0xffffffffu, rs, off);
            rl[i] = rl[i] * pscale + rs;
            #pragma unroll
            for (int j = 0; j < 8; j++) o[i][j] *= pscale;
        }

        // store P transposed
        #pragma unroll
        for (int j = 0; j < 4; j++)
            #pragma unroll
            for (int i = 0; i < 4; i++)
                Pt[(tx * 4 + j) * 68 + ty * 4 + i] = s[i][j];
        __syncthreads();

        // O += P @ V
        for (int n = 0; n < 64; n++) {
            float4 a = *(float4*)&Pt[n * 68 + ty * 4];
            float4 b0 = *(float4*)&Vs[n * 128 + tx * 4];
            float4 b1 = *(float4*)&Vs[n * 128 + 64 + tx * 4];
            float av[4] = {a.x, a.y, a.z, a.w};
            float bv0[4] = {b0.x, b0.y, b0.z, b0.w};
            float bv1[4] = {b1.x, b1.y, b1.z, b1.w};
            #pragma unroll
            for (int i = 0; i < 4; i++) {
                #pragma unroll
                for (int j = 0; j < 4; j++) {
                    o[i][j]     += av[i] * bv0[j];
                    o[i][4 + j] += av[i] * bv1[j];
                }
            }
        }
        __syncthreads();
    }

    // write out: o / (l * 16)
    #pragma unroll
    for (int i = 0; i < 4; i++) {
        int row = m0 + ty * 4 + i;
        if (row >= NTOK) continue;
        float inv = 1.f / (rl[i] * 16.f);
        float* outp = g_o + ((size_t)b * NTOK + row) * EMBD + h * DH;
        float4 v0, v1;
        v0.x = o[i][0] * inv; v0.y = o[i][1] * inv; v0.z = o[i][2] * inv; v0.w = o[i][3] * inv;
        v1.x = o[i][4] * inv; v1.y = o[i][5] * inv; v1.z = o[i][6] * inv; v1.w = o[i][7] * inv;
        *(float4*)(outp + tx * 4) = v0;
        *(float4*)(outp + 64 + tx * 4) = v1;
    }
}

// ---------------- head ----------------
__global__ void head_kernel(const float* __restrict__ lg, const float* __restrict__ lb,
                            const float* __restrict__ Wc, const float* __restrict__ bc,
                            float* __restrict__ out) {
    __shared__ float sh[8];
    int b = blockIdx.x;
    int c = threadIdx.x;
    const float* zb = g_z + (size_t)b * NTOK * EMBD;
    float s = 0.f;
    for (int n = 0; n < NTOK; n++) s += zb[(size_t)n * EMBD + c];
    float pooled = s * (1.f / NTOK);
    float mean = block_sum_256(pooled, sh) * (1.f / EMBD);
    float d = pooled - mean;
    float var = block_sum_256(d * d, sh) * (1.f / EMBD);
    float ln = d * rsqrtf(var + 1e-5f) * lg[c] + lb[c];
    float l0 = block_sum_256(ln * Wc[c * 2 + 0], sh);
    float l1 = block_sum_256(ln * Wc[c * 2 + 1], sh);
    if (c == 0) {
        l0 += bc[0];
        l1 += bc[1];
        float mx = fmaxf(l0, l1);
        float lse = mx + logf(expf(l0 - mx) + expf(l1 - mx));
        out[b * 2 + 0] = l0 - lse;
        out[b * 2 + 1] = l1 - lse;
    }
}

// ---------------- launch ----------------
extern "C" void kernel_launch(void* const* d_in, const int* in_sizes, int n_in,
                              void* d_out, int out_size) {
    const float* x    = (const float*)d_in[0];
    const float* W1   = (const float*)d_in[1];
    const float* b1   = (const float*)d_in[2];
    const float* cls1 = (const float*)d_in[3];
    const float* W2   = (const float*)d_in[4];
    const float* b2   = (const float*)d_in[5];
    const float* cls2 = (const float*)d_in[6];
    const float* ln1g = (const float*)d_in[7];
    const float* ln1b = (const float*)d_in[8];
    const float* Wq   = (const float*)d_in[9];
    const float* bq   = (const float*)d_in[10];
    const float* Wk   = (const float*)d_in[11];
    const float* bk   = (const float*)d_in[12];
    const float* Wv   = (const float*)d_in[13];
    const float* bv   = (const float*)d_in[14];
    const float* Wp   = (const float*)d_in[15];
    const float* bp   = (const float*)d_in[16];
    const float* ln2g = (const float*)d_in[17];
    const float* ln2b = (const float*)d_in[18];
    const float* lncg = (const float*)d_in[19];
    const float* lncb = (const float*)d_in[20];
    const float* Wc   = (const float*)d_in[21];
    const float* bc   = (const float*)d_in[22];
    float* out = (float*)d_out;

    float *p1, *p2, *e1, *e2, *zp, *hp, *qkvp, *oo, *op_, *wqkv, *bqkv;
    cudaGetSymbolAddress((void**)&p1, g_patch1);
    cudaGetSymbolAddress((void**)&p2, g_patch2);
    cudaGetSymbolAddress((void**)&e1, g_emb1);
    cudaGetSymbolAddress((void**)&e2, g_emb2);
    cudaGetSymbolAddress((void**)&zp, g_z);
    cudaGetSymbolAddress((void**)&hp, g_h);
    cudaGetSymbolAddress((void**)&qkvp, g_qkv);
    cudaGetSymbolAddress((void**)&oo, g_o);
    cudaGetSymbolAddress((void**)&op_, g_op);
    cudaGetSymbolAddress((void**)&wqkv, g_Wqkv);
    cudaGetSymbolAddress((void**)&bqkv, g_bqkv);

    cudaFuncSetAttribute(flash_attn_kernel,
                         cudaFuncAttributeMaxDynamicSharedMemorySize, FA_SMEM);

    im2row1_kernel<<<(ROWS_E * K1) / 256, 256>>>(x);
    im2row2_kernel<<<(ROWS_E * K2) / 256, 256>>>(x);
    concat_qkvw<<<(256 * 768) / 256, 256>>>(Wq, Wk, Wv, bq, bk, bv);

    // patch embeds
    gemm128<<<dim3(EMBD / 128, ROWS_E / 128), 256>>>(p1, W1, nullptr, e1, ROWS_E, EMBD, K1);
    gemm128<<<dim3(EMBD / 128, ROWS_E / 128), 256>>>(p2, W2, nullptr, e2, ROWS_E, EMBD, K2);

    assemble_kernel<<<dim3(NTOK, BATCH), 256>>>(b1, cls1, b2, cls2);
    ln_kernel<<<ROWS_T, 256>>>(zp, ln1g, ln1b, hp);

    // fused QKV
    gemm128<<<dim3(768 / 128, ROWS_T / 128), 256>>>(hp, wqkv, bqkv, qkvp, ROWS_T, 768, EMBD);

    // fused attention (writes g_o)
    flash_attn_kernel<<<dim3(7, BATCH * HEADS), 256, FA_SMEM>>>();

    // output projection
    gemm128<<<dim3(EMBD / 128, ROWS_T / 128), 256>>>(oo, Wp, bp, op_, ROWS_T, EMBD, EMBD);

    ln_res_kernel<<<ROWS_T, 256>>>(ln2g, ln2b);
    head_kernel<<<BATCH, 256>>>(lncg, lncb, Wc, bc, out);
}

// round 7
// speedup vs baseline: 1.4577x; 1.1343x over previous
#include <cuda_runtime.h>
#include <cuda_bf16.h>
#include <cstdint>
#include <math.h>

// ---------------- problem constants ----------------
#define BATCH   128
#define NTOK    394
#define EMBD    256
#define NP      196
#define HEADS   2
#define DH      128
#define K1      768
#define K2      192
#define ROWS_E  (BATCH*NP)         // 25088
#define ROWS_T  (BATCH*NTOK)       // 50432

// ---------------- scratch ----------------
__device__ float g_patch1[(size_t)ROWS_E * K1];
__device__ float g_patch2[(size_t)ROWS_E * K2];
__device__ float g_emb1 [(size_t)ROWS_E * EMBD];
__device__ float g_emb2 [(size_t)ROWS_E * EMBD];
__device__ float g_z    [(size_t)ROWS_T * EMBD];
__device__ float g_h    [(size_t)ROWS_T * EMBD];
__device__ float g_qkv  [(size_t)ROWS_T * 768];
__device__ float g_o    [(size_t)ROWS_T * EMBD];
__device__ float g_op   [(size_t)ROWS_T * EMBD];
__device__ float g_Wqkv [(size_t)EMBD * 768];
__device__ float g_bqkv [768];

// ---------------- block reductions ----------------
__device__ __forceinline__ float block_sum_256(float v, float* sh) {
    #pragma unroll
    for (int o = 16; o > 0; o >>= 1) v += __shfl_xor_sync(0xffffffffu, v, o);
    __syncthreads();
    if ((threadIdx.x & 31) == 0) sh[threadIdx.x >> 5] = v;
    __syncthreads();
    float r = 0.f;
    #pragma unroll
    for (int i = 0; i < 8; i++) r += sh[i];
    return r;
}

// ---------------- im2row ----------------
__global__ void im2row1_kernel(const float* __restrict__ x) {
    int idx = blockIdx.x * 256 + threadIdx.x;
    int f = idx % K1;
    int r = idx / K1;
    int b = r / NP, i = r % NP;
    int hi = i / 14, wi = i % 14;
    int pr = f / 48; int rem = f % 48; int pc = rem / 3; int c = rem % 3;
    g_patch1[idx] = x[(((size_t)b * 3 + c) * 224 + (hi * 16 + pr)) * 224 + (wi * 16 + pc)];
}

__global__ void im2row2_kernel(const float* __restrict__ x) {
    int idx = blockIdx.x * 256 + threadIdx.x;
    int f = idx % K2;
    int r = idx / K2;
    int b = r / NP, j = r % NP;
    int m = 4 * j + 3;
    int hi = m / 28, wi = m % 28;
    int pr = f / 24; int rem = f % 24; int pc = rem / 3; int c = rem % 3;
    g_patch2[idx] = x[(((size_t)b * 3 + c) * 224 + (hi * 8 + pr)) * 224 + (wi * 8 + pc)];
}

// ---------------- QKV weight concat ----------------
__global__ void concat_qkvw(const float* __restrict__ Wq, const float* __restrict__ Wk,
                            const float* __restrict__ Wv, const float* __restrict__ bq,
                            const float* __restrict__ bk, const float* __restrict__ bv) {
    int idx = blockIdx.x * 256 + threadIdx.x;
    int r = idx / 768, c = idx % 768;
    const float* src = (c < 256) ? Wq : ((c < 512) ? Wk : Wv);
    int cc = c & 255;
    g_Wqkv[idx] = src[r * 256 + cc];
    if (r == 0) g_bqkv[c] = ((c < 256) ? bq : ((c < 512) ? bk : bv))[cc];
}

// ---------------- bf16 split helpers ----------------
// pack (x = k-even, y = k-odd) into bf16x2 hi + bf16x2 lo (residual).
__device__ __forceinline__ void split2(float x, float y, uint32_t& hi, uint32_t& lo) {
    asm("cvt.rn.bf16x2.f32 %0, %1, %2;" : "=r"(hi) : "f"(y), "f"(x));
    float hx = __uint_as_float(hi << 16);
    float hy = __uint_as_float(hi & 0xffff0000u);
    float lx = x - hx, ly = y - hy;
    asm("cvt.rn.bf16x2.f32 %0, %1, %2;" : "=r"(lo) : "f"(ly), "f"(lx));
}

__device__ __forceinline__ void mma16816(float* c, const uint32_t* a, const uint32_t* b) {
    asm volatile("mma.sync.aligned.m16n8k16.row.col.f32.bf16.bf16.f32 "
                 "{%0,%1,%2,%3}, {%4,%5,%6,%7}, {%8,%9}, {%0,%1,%2,%3};"
                 : "+f"(c[0]), "+f"(c[1]), "+f"(c[2]), "+f"(c[3])
                 : "r"(a[0]), "r"(a[1]), "r"(a[2]), "r"(a[3]), "r"(b[0]), "r"(b[1]));
}

// ---------------- tensor-core GEMM (bf16 split-3, fp32-accurate) ----------------
// C[M,N] = A[M,K] @ B[K,N] (+bias). M%128==0, N%128==0, K%32==0.
// Block 128x128x32, 8 warps (2x4), warp tile 64x32.
#define GP 36   // smem pitch (floats)
#define GEMM_SMEM (4 * 128 * GP * 4)   // 2 bufs x (A + B) = 73728 B

__global__ __launch_bounds__(256, 1)
void gemm_mma(const float* __restrict__ A, const float* __restrict__ B,
              const float* __restrict__ bias, float* __restrict__ C,
              int M, int N, int K) {
    extern __shared__ float sm[];
    float* AsB = sm;
    float* BsB = sm + 2 * 128 * GP;

    int t = threadIdx.x;
    int w = t >> 5, lane = t & 31;
    int g = lane >> 2, tig = lane & 3;
    int wm = (w & 1) * 64, wn = (w >> 1) * 32;

    int m0 = blockIdx.y * 128, n0 = blockIdx.x * 128;
    const float* Ab = A + (size_t)m0 * K;
    const float* Bb = B + n0;

    float4 rA[4], rB[4];

    // prefetch tile 0
    #pragma unroll
    for (int i = 0; i < 4; i++) {
        int idx = i * 256 + t;
        int r = idx >> 3, c4 = (idx & 7) * 4;
        rA[i] = *(const float4*)(Ab + (size_t)r * K + c4);
        int kk = idx >> 5, n4 = (idx & 31) * 4;
        rB[i] = *(const float4*)(Bb + (size_t)kk * N + n4);
    }
    #pragma unroll
    for (int i = 0; i < 4; i++) {
        int idx = i * 256 + t;
        int r = idx >> 3, c4 = (idx & 7) * 4;
        *(float4*)&AsB[r * GP + c4] = rA[i];
        int kk = idx >> 5, n4 = (idx & 31) * 4;
        BsB[(n4 + 0) * GP + kk] = rB[i].x;
        BsB[(n4 + 1) * GP + kk] = rB[i].y;
        BsB[(n4 + 2) * GP + kk] = rB[i].z;
        BsB[(n4 + 3) * GP + kk] = rB[i].w;
    }
    __syncthreads();

    float acc[4][4][4];
    #pragma unroll
    for (int mf = 0; mf < 4; mf++)
        #pragma unroll
        for (int nf = 0; nf < 4; nf++)
            #pragma unroll
            for (int e = 0; e < 4; e++) acc[mf][nf][e] = 0.f;

    int kt = K >> 5;
    for (int tt = 0; tt < kt; tt++) {
        int cur = tt & 1;
        float* As = AsB + cur * 128 * GP;
        float* Bs = BsB + cur * 128 * GP;

        if (tt + 1 < kt) {
            const float* Ap = Ab + (tt + 1) * 32;
            const float* Bp = Bb + (size_t)(tt + 1) * 32 * N;
            #pragma unroll
            for (int i = 0; i < 4; i++) {
                int idx = i * 256 + t;
                int r = idx >> 3, c4 = (idx & 7) * 4;
                rA[i] = *(const float4*)(Ap + (size_t)r * K + c4);
                int kk = idx >> 5, n4 = (idx & 31) * 4;
                rB[i] = *(const float4*)(Bp + (size_t)kk * N + n4);
            }
        }

        #pragma unroll
        for (int ks = 0; ks < 32; ks += 16) {
            uint32_t aHi[4][4], aLo[4][4], bHi[4][2], bLo[4][2];
            #pragma unroll
            for (int mf = 0; mf < 4; mf++) {
                int mr = wm + mf * 16 + g;
                float2 p0 = *(float2*)&As[mr * GP + ks + 2 * tig];
                float2 p1 = *(float2*)&As[(mr + 8) * GP + ks + 2 * tig];
                float2 p2 = *(float2*)&As[mr * GP + ks + 2 * tig + 8];
                float2 p3 = *(float2*)&As[(mr + 8) * GP + ks + 2 * tig + 8];
                split2(p0.x, p0.y, aHi[mf][0], aLo[mf][0]);
                split2(p1.x, p1.y, aHi[mf][1], aLo[mf][1]);
                split2(p2.x, p2.y, aHi[mf][2], aLo[mf][2]);
                split2(p3.x, p3.y, aHi[mf][3], aLo[mf][3]);
            }
            #pragma unroll
            for (int nf = 0; nf < 4; nf++) {
                int nc = wn + nf * 8 + g;
                float2 q0 = *(float2*)&Bs[nc * GP + ks + 2 * tig];
                float2 q1 = *(float2*)&Bs[nc * GP + ks + 2 * tig + 8];
                split2(q0.x, q0.y, bHi[nf][0], bLo[nf][0]);
                split2(q1.x, q1.y, bHi[nf][1], bLo[nf][1]);
            }
            #pragma unroll
            for (int mf = 0; mf < 4; mf++)
                #pragma unroll
                for (int nf = 0; nf < 4; nf++) {
                    mma16816(acc[mf][nf], aHi[mf], bHi[nf]);
                    mma16816(acc[mf][nf], aHi[mf], bLo[nf]);
                    mma16816(acc[mf][nf], aLo[mf], bHi[nf]);
                }
        }

        if (tt + 1 < kt) {
            int nxt = cur ^ 1;
            float* An = AsB + nxt * 128 * GP;
            float* Bn = BsB + nxt * 128 * GP;
            #pragma unroll
            for (int i = 0; i < 4; i++) {
                int idx = i * 256 + t;
                int r = idx >> 3, c4 = (idx & 7) * 4;
                *(float4*)&An[r * GP + c4] = rA[i];
                int kk = idx >> 5, n4 = (idx & 31) * 4;
                Bn[(n4 + 0) * GP + kk] = rB[i].x;
                Bn[(n4 + 1) * GP + kk] = rB[i].y;
                Bn[(n4 + 2) * GP + kk] = rB[i].z;
                Bn[(n4 + 3) * GP + kk] = rB[i].w;
            }
        }
        __syncthreads();
    }

    // writeback
    #pragma unroll
    for (int mf = 0; mf < 4; mf++) {
        int r0 = m0 + wm + mf * 16 + g;
        #pragma unroll
        for (int nf = 0; nf < 4; nf++) {
            int c0 = n0 + wn + nf * 8 + 2 * tig;
            float2 v0, v1;
            v0.x = acc[mf][nf][0]; v0.y = acc[mf][nf][1];
            v1.x = acc[mf][nf][2]; v1.y = acc[mf][nf][3];
            if (bias) {
                float2 bb = *(const float2*)(bias + c0);
                v0.x += bb.x; v0.y += bb.y;
                v1.x += bb.x; v1.y += bb.y;
            }
            *(float2*)(C + (size_t)r0 * N + c0) = v0;
            *(float2*)(C + (size_t)(r0 + 8) * N + c0) = v1;
        }
    }
}

// ---------------- assemble z = concat(p2r, p1) ----------------
__global__ void assemble_kernel(const float* __restrict__ b1, const float* __restrict__ cls1,
                                const float* __restrict__ b2, const float* __restrict__ cls2) {
    int n = blockIdx.x;
    int b = blockIdx.y;
    int c = threadIdx.x;
    float val;
    if (n == 0)            val = cls2[c];
    else if (n <= NP)      val = g_emb2[((size_t)(b * NP + (n - 1))) * EMBD + c] + b2[c];
    else if (n == NP + 1)  val = cls1[c];
    else                   val = g_emb1[((size_t)(b * NP + (n - NP - 2))) * EMBD + c] + b1[c];
    g_z[((size_t)b * NTOK + n) * EMBD + c] = val;
}

// ---------------- layer norms ----------------
__global__ void ln_kernel(const float* __restrict__ in, const float* __restrict__ gw,
                          const float* __restrict__ bw, float* __restrict__ out) {
    __shared__ float sh[8];
    long long row = blockIdx.x;
    int c = threadIdx.x;
    float v = in[row * EMBD + c];
    float mean = block_sum_256(v, sh) * (1.f / EMBD);
    float d = v - mean;
    float var = block_sum_256(d * d, sh) * (1.f / EMBD);
    out[row * EMBD + c] = d * rsqrtf(var + 1e-5f) * gw[c] + bw[c];
}

__global__ void ln_res_kernel(const float* __restrict__ gw, const float* __restrict__ bw) {
    __shared__ float sh[8];
    long long row = blockIdx.x;
    int c = threadIdx.x;
    float v = g_op[row * EMBD + c];
    float mean = block_sum_256(v, sh) * (1.f / EMBD);
    float d = v - mean;
    float var = block_sum_256(d * d, sh) * (1.f / EMBD);
    g_z[row * EMBD + c] += d * rsqrtf(var + 1e-5f) * gw[c] + bw[c];
}

// ---------------- fused flash attention (fp32) ----------------
#define FA_SMEM ((128*68 + 128*68 + 64*128 + 64*68) * 4)

__global__ __launch_bounds__(256, 1)
void flash_attn_kernel() {
    extern __shared__ float fsm[];
    float* Qt = fsm;
    float* Kt = Qt + 128 * 68;
    float* Vs = Kt + 128 * 68;
    float* Pt = Vs + 64 * 128;

    int tid = threadIdx.x;
    int tx = tid & 15, ty = tid >> 4;
    int m0 = blockIdx.x * 64;
    int bh = blockIdx.y;
    int b = bh >> 1, h = bh & 1;

    const float* base = g_qkv + (size_t)b * NTOK * 768;
    const float* qb = base + h * DH;
    const float* kb = base + 256 + h * DH;
    const float* vb = base + 512 + h * DH;

    for (int i = tid; i < 64 * 32; i += 256) {
        int r = i >> 5, d4 = (i & 31) * 4;
        float4 v = make_float4(0.f, 0.f, 0.f, 0.f);
        if (m0 + r < NTOK) v = *(const float4*)(qb + (size_t)(m0 + r) * 768 + d4);
        Qt[(d4 + 0) * 68 + r] = v.x;
        Qt[(d4 + 1) * 68 + r] = v.y;
        Qt[(d4 + 2) * 68 + r] = v.z;
        Qt[(d4 + 3) * 68 + r] = v.w;
    }

    float o[4][8];
    #pragma unroll
    for (int i = 0; i < 4; i++)
        #pragma unroll
        for (int j = 0; j < 8; j++) o[i][j] = 0.f;
    float rm[4], rl[4];
    #pragma unroll
    for (int i = 0; i < 4; i++) { rm[i] = -1e30f; rl[i] = 0.f; }

    for (int nt = 0; nt < 7; nt++) {
        int n0c = nt * 64;
        for (int i = tid; i < 64 * 32; i += 256) {
            int r = i >> 5, d4 = (i & 31) * 4;
            float4 v = make_float4(0.f, 0.f, 0.f, 0.f);
            if (n0c + r < NTOK) v = *(const float4*)(kb + (size_t)(n0c + r) * 768 + d4);
            Kt[(d4 + 0) * 68 + r] = v.x;
            Kt[(d4 + 1) * 68 + r] = v.y;
            Kt[(d4 + 2) * 68 + r] = v.z;
            Kt[(d4 + 3) * 68 + r] = v.w;
            float4 w = make_float4(0.f, 0.f, 0.f, 0.f);
            if (n0c + r < NTOK) w = *(const float4*)(vb + (size_t)(n0c + r) * 768 + d4);
            *(float4*)&Vs[r * 128 + d4] = w;
        }
        __syncthreads();

        float s[4][4];
        #pragma unroll
        for (int i = 0; i < 4; i++)
            #pragma unroll
            for (int j = 0; j < 4; j++) s[i][j] = 0.f;
        for (int d = 0; d < 128; d++) {
            float4 a = *(float4*)&Qt[d * 68 + ty * 4];
            float4 bb = *(float4*)&Kt[d * 68 + tx * 4];
            float av[4] = {a.x, a.y, a.z, a.w};
            float bv_[4] = {bb.x, bb.y, bb.z, bb.w};
            #pragma unroll
            for (int i = 0; i < 4; i++)
                #pragma unroll
                for (int j = 0; j < 4; j++)
                    s[i][j] += av[i] * bv_[j];
        }
        #pragma unroll
        for (int j = 0; j < 4; j++)
            if (n0c + tx * 4 + j >= NTOK)
                #pragma unroll
                for (int i = 0; i < 4; i++) s[i][j] = -1e30f;

        #pragma unroll
        for (int i = 0; i < 4; i++) {
            float cm = fmaxf(fmaxf(s[i][0], s[i][1]), fmaxf(s[i][2], s[i][3]));
            #pragma unroll
            for (int off = 8; off > 0; off >>= 1)
                cm = fmaxf(cm, __shfl_xor_sync(0xffffffffu, cm, off));
            float newm = fmaxf(rm[i], cm);
            float pscale = __expf(rm[i] - newm);
            rm[i] = newm;
            float rs = 0.f;
            #pragma unroll
            for (int j = 0; j < 4; j++) {
                s[i][j] = __expf(s[i][j] - newm);
                rs += s[i][j];
            }
            #pragma unroll
            for (int off = 8; off > 0; off >>= 1)
                rs += __shfl_xor_sync(0xffffffffu, rs, off);
            rl[i] = rl[i] * pscale + rs;
            #pragma unroll
            for (int j = 0; j < 8; j++) o[i][j] *= pscale;
        }

        #pragma unroll
        for (int j = 0; j < 4; j++)
            #pragma unroll
            for (int i = 0; i < 4; i++)
                Pt[(tx * 4 + j) * 68 + ty * 4 + i] = s[i][j];
        __syncthreads();

        for (int n = 0; n < 64; n++) {
            float4 a = *(float4*)&Pt[n * 68 + ty * 4];
            float4 b0 = *(float4*)&Vs[n * 128 + tx * 4];
            float4 b1 = *(float4*)&Vs[n * 128 + 64 + tx * 4];
            float av[4] = {a.x, a.y, a.z, a.w};
            float bv0[4] = {b0.x, b0.y, b0.z, b0.w};
            float bv1[4] = {b1.x, b1.y, b1.z, b1.w};
            #pragma unroll
            for (int i = 0; i < 4; i++) {
                #pragma unroll
                for (int j = 0; j < 4; j++) {
                    o[i][j]     += av[i] * bv0[j];
                    o[i][4 + j] += av[i] * bv1[j];
                }
            }
        }
        __syncthreads();
    }

    #pragma unroll
    for (int i = 0; i < 4; i++) {
        int row = m0 + ty * 4 + i;
        if (row >= NTOK) continue;
        float inv = 1.f / (rl[i] * 16.f);
        float* outp = g_o + ((size_t)b * NTOK + row) * EMBD + h * DH;
        float4 v0, v1;
        v0.x = o[i][0] * inv; v0.y = o[i][1] * inv; v0.z = o[i][2] * inv; v0.w = o[i][3] * inv;
        v1.x = o[i][4] * inv; v1.y = o[i][5] * inv; v1.z = o[i][6] * inv; v1.w = o[i][7] * inv;
        *(float4*)(outp + tx * 4) = v0;
        *(float4*)(outp + 64 + tx * 4) = v1;
    }
}

// ---------------- head ----------------
__global__ void head_kernel(const float* __restrict__ lg, const float* __restrict__ lb,
                            const float* __restrict__ Wc, const float* __restrict__ bc,
                            float* __restrict__ out) {
    __shared__ float sh[8];
    int b = blockIdx.x;
    int c = threadIdx.x;
    const float* zb = g_z + (size_t)b * NTOK * EMBD;
    float s = 0.f;
    for (int n = 0; n < NTOK; n++) s += zb[(size_t)n * EMBD + c];
    float pooled = s * (1.f / NTOK);
    float mean = block_sum_256(pooled, sh) * (1.f / EMBD);
    float d = pooled - mean;
    float var = block_sum_256(d * d, sh) * (1.f / EMBD);
    float ln = d * rsqrtf(var + 1e-5f) * lg[c] + lb[c];
    float l0 = block_sum_256(ln * Wc[c * 2 + 0], sh);
    float l1 = block_sum_256(ln * Wc[c * 2 + 1], sh);
    if (c == 0) {
        l0 += bc[0];
        l1 += bc[1];
        float mx = fmaxf(l0, l1);
        float lse = mx + logf(expf(l0 - mx) + expf(l1 - mx));
        out[b * 2 + 0] = l0 - lse;
        out[b * 2 + 1] = l1 - lse;
    }
}

// ---------------- launch ----------------
extern "C" void kernel_launch(void* const* d_in, const int* in_sizes, int n_in,
                              void* d_out, int out_size) {
    const float* x    = (const float*)d_in[0];
    const float* W1   = (const float*)d_in[1];
    const float* b1   = (const float*)d_in[2];
    const float* cls1 = (const float*)d_in[3];
    const float* W2   = (const float*)d_in[4];
    const float* b2   = (const float*)d_in[5];
    const float* cls2 = (const float*)d_in[6];
    const float* ln1g = (const float*)d_in[7];
    const float* ln1b = (const float*)d_in[8];
    const float* Wq   = (const float*)d_in[9];
    const float* bq   = (const float*)d_in[10];
    const float* Wk   = (const float*)d_in[11];
    const float* bk   = (const float*)d_in[12];
    const float* Wv   = (const float*)d_in[13];
    const float* bv   = (const float*)d_in[14];
    const float* Wp   = (const float*)d_in[15];
    const float* bp   = (const float*)d_in[16];
    const float* ln2g = (const float*)d_in[17];
    const float* ln2b = (const float*)d_in[18];
    const float* lncg = (const float*)d_in[19];
    const float* lncb = (const float*)d_in[20];
    const float* Wc   = (const float*)d_in[21];
    const float* bc   = (const float*)d_in[22];
    float* out = (float*)d_out;

    float *p1, *p2, *e1, *e2, *zp, *hp, *qkvp, *oo, *op_, *wqkv, *bqkv;
    cudaGetSymbolAddress((void**)&p1, g_patch1);
    cudaGetSymbolAddress((void**)&p2, g_patch2);
    cudaGetSymbolAddress((void**)&e1, g_emb1);
    cudaGetSymbolAddress((void**)&e2, g_emb2);
    cudaGetSymbolAddress((void**)&zp, g_z);
    cudaGetSymbolAddress((void**)&hp, g_h);
    cudaGetSymbolAddress((void**)&qkvp, g_qkv);
    cudaGetSymbolAddress((void**)&oo, g_o);
    cudaGetSymbolAddress((void**)&op_, g_op);
    cudaGetSymbolAddress((void**)&wqkv, g_Wqkv);
    cudaGetSymbolAddress((void**)&bqkv, g_bqkv);

    cudaFuncSetAttribute(flash_attn_kernel,
                         cudaFuncAttributeMaxDynamicSharedMemorySize, FA_SMEM);
    cudaFuncSetAttribute(gemm_mma,
                         cudaFuncAttributeMaxDynamicSharedMemorySize, GEMM_SMEM);

    im2row1_kernel<<<(ROWS_E * K1) / 256, 256>>>(x);
    im2row2_kernel<<<(ROWS_E * K2) / 256, 256>>>(x);
    concat_qkvw<<<(256 * 768) / 256, 256>>>(Wq, Wk, Wv, bq, bk, bv);

    // patch embeds (tensor cores)
    gemm_mma<<<dim3(EMBD / 128, ROWS_E / 128), 256, GEMM_SMEM>>>(p1, W1, nullptr, e1, ROWS_E, EMBD, K1);
    gemm_mma<<<dim3(EMBD / 128, ROWS_E / 128), 256, GEMM_SMEM>>>(p2, W2, nullptr, e2, ROWS_E, EMBD, K2);

    assemble_kernel<<<dim3(NTOK, BATCH), 256>>>(b1, cls1, b2, cls2);
    ln_kernel<<<ROWS_T, 256>>>(zp, ln1g, ln1b, hp);

    // fused QKV (tensor cores)
    gemm_mma<<<dim3(768 / 128, ROWS_T / 128), 256, GEMM_SMEM>>>(hp, wqkv, bqkv, qkvp, ROWS_T, 768, EMBD);

    // fused attention (writes g_o)
    flash_attn_kernel<<<dim3(7, BATCH * HEADS), 256, FA_SMEM>>>();

    // output projection (tensor cores)
    gemm_mma<<<dim3(EMBD / 128, ROWS_T / 128), 256, GEMM_SMEM>>>(oo, Wp, bp, op_, ROWS_T, EMBD, EMBD);

    ln_res_kernel<<<ROWS_T, 256>>>(ln2g, ln2b);
    head_kernel<<<BATCH, 256>>>(lncg, lncb, Wc, bc, out);
}

// round 9
// speedup vs baseline: 2.8007x; 1.9214x over previous
#include <cuda_runtime.h>
#include <cuda_bf16.h>
#include <cstdint>
#include <math.h>

// ---------------- problem constants ----------------
#define BATCH   128
#define NTOK    394
#define EMBD    256
#define NP      196
#define HEADS   2
#define DH      128
#define K1      768
#define K2      192
#define ROWS_E  (BATCH*NP)         // 25088
#define ROWS_T  (BATCH*NTOK)       // 50432

// ---------------- scratch ----------------
__device__ __nv_bfloat16 g_p1h[(size_t)ROWS_E * K1];
__device__ __nv_bfloat16 g_p1l[(size_t)ROWS_E * K1];
__device__ __nv_bfloat16 g_p2h[(size_t)ROWS_E * K2];
__device__ __nv_bfloat16 g_p2l[(size_t)ROWS_E * K2];
__device__ __nv_bfloat16 g_hh [(size_t)ROWS_T * EMBD];
__device__ __nv_bfloat16 g_hl [(size_t)ROWS_T * EMBD];
__device__ __nv_bfloat16 g_oh [(size_t)ROWS_T * EMBD];
__device__ __nv_bfloat16 g_ol [(size_t)ROWS_T * EMBD];
__device__ __nv_bfloat16 g_w1h[256 * 768], g_w1l[256 * 768];
__device__ __nv_bfloat16 g_w2h[256 * 192], g_w2l[256 * 192];
__device__ __nv_bfloat16 g_wqh[768 * 256], g_wql[768 * 256];
__device__ __nv_bfloat16 g_wph[256 * 256], g_wpl[256 * 256];
__device__ float g_bqkv[768];
__device__ float g_emb1[(size_t)ROWS_E * EMBD];
__device__ float g_emb2[(size_t)ROWS_E * EMBD];
__device__ float g_z   [(size_t)ROWS_T * EMBD];
__device__ float g_qkv [(size_t)ROWS_T * 768];
__device__ float g_op  [(size_t)ROWS_T * EMBD];

// ---------------- helpers ----------------
__device__ __forceinline__ uint32_t smem_u32(const void* p) {
    return (uint32_t)__cvta_generic_to_shared(p);
}

// pack (x -> low half, y -> high half) to bf16x2 hi + residual lo
__device__ __forceinline__ void split2(float x, float y, uint32_t& hi, uint32_t& lo) {
    asm("cvt.rn.bf16x2.f32 %0, %1, %2;" : "=r"(hi) : "f"(y), "f"(x));
    float hx = __uint_as_float(hi << 16);
    float hy = __uint_as_float(hi & 0xffff0000u);
    float lx = x - hx, ly = y - hy;
    asm("cvt.rn.bf16x2.f32 %0, %1, %2;" : "=r"(lo) : "f"(ly), "f"(lx));
}

__device__ __forceinline__ void split1(float v, __nv_bfloat16& hi, __nv_bfloat16& lo) {
    hi = __float2bfloat16(v);
    lo = __float2bfloat16(v - __bfloat162float(hi));
}

__device__ __forceinline__ void mma16816(float* c, const uint32_t* a, const uint32_t* b) {
    asm volatile("mma.sync.aligned.m16n8k16.row.col.f32.bf16.bf16.f32 "
                 "{%0,%1,%2,%3}, {%4,%5,%6,%7}, {%8,%9}, {%0,%1,%2,%3};"
                 : "+f"(c[0]), "+f"(c[1]), "+f"(c[2]), "+f"(c[3])
                 : "r"(a[0]), "r"(a[1]), "r"(a[2]), "r"(a[3]), "r"(b[0]), "r"(b[1]));
}

__device__ __forceinline__ void ldsm4v(uint32_t* r, uint32_t addr) {
    asm volatile("ldmatrix.sync.aligned.m8n8.x4.shared.b16 {%0,%1,%2,%3}, [%4];"
        : "=r"(r[0]), "=r"(r[1]), "=r"(r[2]), "=r"(r[3]) : "r"(addr));
}

// exp on the FMA pipe (avoids MUFU throughput floor); valid for x <= 0
__device__ __forceinline__ float fast_exp(float x) {
    float y = x * 1.4426950408889634f;
    float n = rintf(y);
    float f = y - n;
    float p = 1.3333558146e-3f;
    p = fmaf(p, f, 9.6181291076e-3f);
    p = fmaf(p, f, 5.5504108664e-2f);
    p = fmaf(p, f, 2.4022650696e-1f);
    p = fmaf(p, f, 6.9314718056e-1f);
    p = fmaf(p, f, 1.0f);
    int e = (int)n;
    float r = __int_as_float((uint32_t)(e + 127) << 23) * p;
    return (n < -125.f) ? 0.f : r;
}

__device__ __forceinline__ float block_sum_256(float v, float* sh) {
    #pragma unroll
    for (int o = 16; o > 0; o >>= 1) v += __shfl_xor_sync(0xffffffffu, v, o);
    __syncthreads();
    if ((threadIdx.x & 31) == 0) sh[threadIdx.x >> 5] = v;
    __syncthreads();
    float r = 0.f;
    #pragma unroll
    for (int i = 0; i < 8; i++) r += sh[i];
    return r;
}

// ---------------- im2row (writes split bf16) ----------------
__global__ void im2row1_kernel(const float* __restrict__ x) {
    int idx = blockIdx.x * 256 + threadIdx.x;
    int f = idx % K1;
    int r = idx / K1;
    int b = r / NP, i = r % NP;
    int hi = i / 14, wi = i % 14;
    int pr = f / 48; int rem = f % 48; int pc = rem / 3; int c = rem % 3;
    float val = x[(((size_t)b * 3 + c) * 224 + (hi * 16 + pr)) * 224 + (wi * 16 + pc)];
    __nv_bfloat16 h_, l_;
    split1(val, h_, l_);
    g_p1h[idx] = h_; g_p1l[idx] = l_;
}

__global__ void im2row2_kernel(const float* __restrict__ x) {
    int idx = blockIdx.x * 256 + threadIdx.x;
    int f = idx % K2;
    int r = idx / K2;
    int b = r / NP, j = r % NP;
    int m = 4 * j + 3;
    int hi = m / 28, wi = m % 28;
    int pr = f / 24; int rem = f % 24; int pc = rem / 3; int c = rem % 3;
    float val = x[(((size_t)b * 3 + c) * 224 + (hi * 8 + pr)) * 224 + (wi * 8 + pc)];
    __nv_bfloat16 h_, l_;
    split1(val, h_, l_);
    g_p2h[idx] = h_; g_p2l[idx] = l_;
}

// ---------------- weight prep: transpose + split ----------------
// W [Kd][Nd] fp32 -> out [Nd][Kd] bf16 hi/lo
__global__ void wsplit_kernel(const float* __restrict__ W, __nv_bfloat16* __restrict__ oh,
                              __nv_bfloat16* __restrict__ ol, int Kd, int Nd) {
    int idx = blockIdx.x * 256 + threadIdx.x;
    if (idx >= Kd * Nd) return;
    int n = idx / Kd, k = idx % Kd;
    __nv_bfloat16 h_, l_;
    split1(W[k * Nd + n], h_, l_);
    oh[idx] = h_; ol[idx] = l_;
}

__global__ void wqkv_split(const float* __restrict__ Wq, const float* __restrict__ Wk,
                           const float* __restrict__ Wv, const float* __restrict__ bq,
                           const float* __restrict__ bk, const float* __restrict__ bv) {
    int idx = blockIdx.x * 256 + threadIdx.x;   // 768*256
    int n = idx >> 8, k = idx & 255;
    const float* src = (n < 256) ? Wq : ((n < 512) ? Wk : Wv);
    __nv_bfloat16 h_, l_;
    split1(src[k * 256 + (n & 255)], h_, l_);
    g_wqh[idx] = h_; g_wql[idx] = l_;
    if (idx < 768) g_bqkv[idx] = ((idx < 256) ? bq : ((idx < 512) ? bk : bv))[idx & 255];
}

// ---------------- bf16 tensor-core GEMM, operands pre-split ----------------
// C[M,N] = (Ah+Al)[M,K] @ (Bh+Bl)^T  where B given as [N][K].  3-pass split accum.
#define GAP  40
#define GSTG (4 * 128 * GAP)             // elems per stage
#define GEMM2_SMEM (2 * GSTG * 2)        // 81920 bytes

__global__ __launch_bounds__(256)
void gemm_mma2(const __nv_bfloat16* __restrict__ Ah, const __nv_bfloat16* __restrict__ Al,
               const __nv_bfloat16* __restrict__ Bh, const __nv_bfloat16* __restrict__ Bl,
               const float* __restrict__ bias, float* __restrict__ C,
               int M, int N, int K) {
    extern __shared__ __nv_bfloat16 gsm[];
    uint32_t sbase = smem_u32(gsm);
    int t = threadIdx.x, lane = t & 31, w = t >> 5;
    int g = lane >> 2, tig = lane & 3;
    int wm = (w & 1) * 64, wn = (w >> 1) * 32;
    int m0 = blockIdx.y * 128, n0 = blockIdx.x * 128;
    const __nv_bfloat16* Abh = Ah + (size_t)m0 * K;
    const __nv_bfloat16* Abl = Al + (size_t)m0 * K;
    const __nv_bfloat16* Bbh = Bh + (size_t)n0 * K;
    const __nv_bfloat16* Bbl = Bl + (size_t)n0 * K;

    int a_row = (lane & 7) + ((lane >> 3) & 1) * 8;
    int a_col = ((lane >> 4) & 1) * 8;
    int b_row = (lane & 7) + ((lane >> 4) & 1) * 8;
    int b_col = ((lane >> 3) & 1) * 8;

    uint4 pA[2], pAl[2], pB[2], pBl[2];

    // prefetch k-tile 0
    #pragma unroll
    for (int j = 0; j < 2; j++) {
        int i = t + 256 * j;
        int r = i >> 2, c8 = (i & 3) * 8;
        pA[j]  = *(const uint4*)(Abh + (size_t)r * K + c8);
        pAl[j] = *(const uint4*)(Abl + (size_t)r * K + c8);
        pB[j]  = *(const uint4*)(Bbh + (size_t)r * K + c8);
        pBl[j] = *(const uint4*)(Bbl + (size_t)r * K + c8);
    }
    #pragma unroll
    for (int j = 0; j < 2; j++) {
        int i = t + 256 * j;
        int r = i >> 2, c8 = (i & 3) * 8;
        *(uint4*)(gsm + (size_t)r * GAP + c8)                 = pA[j];
        *(uint4*)(gsm + 128 * GAP + (size_t)r * GAP + c8)     = pAl[j];
        *(uint4*)(gsm + 2 * 128 * GAP + (size_t)r * GAP + c8) = pB[j];
        *(uint4*)(gsm + 3 * 128 * GAP + (size_t)r * GAP + c8) = pBl[j];
    }
    __syncthreads();

    float acc[4][4][4];
    #pragma unroll
    for (int mt = 0; mt < 4; mt++)
        #pragma unroll
        for (int nf = 0; nf < 4; nf++)
            #pragma unroll
            for (int e = 0; e < 4; e++) acc[mt][nf][e] = 0.f;

    int kt = K >> 5;
    for (int tt = 0; tt < kt; tt++) {
        int cur = tt & 1;
        if (tt + 1 < kt) {
            int kb = (tt + 1) * 32;
            #pragma unroll
            for (int j = 0; j < 2; j++) {
                int i = t + 256 * j;
                int r = i >> 2, c8 = (i & 3) * 8;
                pA[j]  = *(const uint4*)(Abh + (size_t)r * K + kb + c8);
                pAl[j] = *(const uint4*)(Abl + (size_t)r * K + kb + c8);
                pB[j]  = *(const uint4*)(Bbh + (size_t)r * K + kb + c8);
                pBl[j] = *(const uint4*)(Bbl + (size_t)r * K + kb + c8);
            }
        }
        uint32_t sA = sbase + cur * GSTG * 2;
        #pragma unroll
        for (int ks = 0; ks < 32; ks += 16) {
            uint32_t ah4[4][4], al4[4][4];
            #pragma unroll
            for (int mt = 0; mt < 4; mt++) {
                uint32_t ad = sA + ((wm + mt * 16 + a_row) * GAP + ks + a_col) * 2;
                ldsm4v(ah4[mt], ad);
                ldsm4v(al4[mt], ad + 128 * GAP * 2);
            }
            uint32_t bh4[2][4], bl4[2][4];
            #pragma unroll
            for (int nt2 = 0; nt2 < 2; nt2++) {
                uint32_t bd = sA + (2 * 128 * GAP + (wn + nt2 * 16 + b_row) * GAP + ks + b_col) * 2;
                ldsm4v(bh4[nt2], bd);
                ldsm4v(bl4[nt2], bd + 128 * GAP * 2);
            }
            #pragma unroll
            for (int mt = 0; mt < 4; mt++)
                #pragma unroll
                for (int nf = 0; nf < 4; nf++) {
                    uint32_t* bhp = &bh4[nf >> 1][(nf & 1) * 2];
                    uint32_t* blp = &bl4[nf >> 1][(nf & 1) * 2];
                    mma16816(acc[mt][nf], ah4[mt], bhp);
                    mma16816(acc[mt][nf], ah4[mt], blp);
                    mma16816(acc[mt][nf], al4[mt], bhp);
                }
        }
        if (tt + 1 < kt) {
            __nv_bfloat16* nb = gsm + ((tt + 1) & 1) * GSTG;
            #pragma unroll
            for (int j = 0; j < 2; j++) {
                int i = t + 256 * j;
                int r = i >> 2, c8 = (i & 3) * 8;
                *(uint4*)(nb + (size_t)r * GAP + c8)                 = pA[j];
                *(uint4*)(nb + 128 * GAP + (size_t)r * GAP + c8)     = pAl[j];
                *(uint4*)(nb + 2 * 128 * GAP + (size_t)r * GAP + c8) = pB[j];
                *(uint4*)(nb + 3 * 128 * GAP + (size_t)r * GAP + c8) = pBl[j];
            }
        }
        __syncthreads();
    }

    #pragma unroll
    for (int mt = 0; mt < 4; mt++) {
        int r0 = m0 + wm + mt * 16 + g;
        #pragma unroll
        for (int nf = 0; nf < 4; nf++) {
            int c0 = n0 + wn + nf * 8 + 2 * tig;
            float2 v0, v1;
            v0.x = acc[mt][nf][0]; v0.y = acc[mt][nf][1];
            v1.x = acc[mt][nf][2]; v1.y = acc[mt][nf][3];
            if (bias) {
                float2 bb = *(const float2*)(bias + c0);
                v0.x += bb.x; v0.y += bb.y;
                v1.x += bb.x; v1.y += bb.y;
            }
            *(float2*)(C + (size_t)r0 * N + c0) = v0;
            *(float2*)(C + (size_t)(r0 + 8) * N + c0) = v1;
        }
    }
}

// ---------------- assemble z = concat(p2r, p1) ----------------
__global__ void assemble_kernel(const float* __restrict__ b1, const float* __restrict__ cls1,
                                const float* __restrict__ b2, const float* __restrict__ cls2) {
    int n = blockIdx.x;
    int b = blockIdx.y;
    int c = threadIdx.x;
    float val;
    if (n == 0)            val = cls2[c];
    else if (n <= NP)      val = g_emb2[((size_t)(b * NP + (n - 1))) * EMBD + c] + b2[c];
    else if (n == NP + 1)  val = cls1[c];
    else                   val = g_emb1[((size_t)(b * NP + (n - NP - 2))) * EMBD + c] + b1[c];
    g_z[((size_t)b * NTOK + n) * EMBD + c] = val;
}

// ---------------- LN (warp per row; writes split bf16 h) ----------------
__global__ void ln_kernel(const float* __restrict__ gw, const float* __restrict__ bw) {
    int wid = threadIdx.x >> 5, lane = threadIdx.x & 31;
    long long row = (long long)blockIdx.x * 8 + wid;
    if (row >= ROWS_T) return;
    const float* p = g_z + row * EMBD;
    float v[8];
    float s = 0.f;
    #pragma unroll
    for (int j = 0; j < 8; j++) { v[j] = p[lane + 32 * j]; s += v[j]; }
    #pragma unroll
    for (int o = 16; o > 0; o >>= 1) s += __shfl_xor_sync(0xffffffffu, s, o);
    float mean = s * (1.f / EMBD);
    float s2 = 0.f;
    #pragma unroll
    for (int j = 0; j < 8; j++) { float d = v[j] - mean; s2 += d * d; }
    #pragma unroll
    for (int o = 16; o > 0; o >>= 1) s2 += __shfl_xor_sync(0xffffffffu, s2, o);
    float inv = rsqrtf(s2 * (1.f / EMBD) + 1e-5f);
    #pragma unroll
    for (int j = 0; j < 8; j++) {
        int c = lane + 32 * j;
        float o = (v[j] - mean) * inv * gw[c] + bw[c];
        __nv_bfloat16 h_, l_;
        split1(o, h_, l_);
        g_hh[row * EMBD + c] = h_;
        g_hl[row * EMBD + c] = l_;
    }
}

// z += LN(op)   (warp per row)
__global__ void ln_res_kernel(const float* __restrict__ gw, const float* __restrict__ bw) {
    int wid = threadIdx.x >> 5, lane = threadIdx.x & 31;
    long long row = (long long)blockIdx.x * 8 + wid;
    if (row >= ROWS_T) return;
    const float* p = g_op + row * EMBD;
    float v[8];
    float s = 0.f;
    #pragma unroll
    for (int j = 0; j < 8; j++) { v[j] = p[lane + 32 * j]; s += v[j]; }
    #pragma unroll
    for (int o = 16; o > 0; o >>= 1) s += __shfl_xor_sync(0xffffffffu, s, o);
    float mean = s * (1.f / EMBD);
    float s2 = 0.f;
    #pragma unroll
    for (int j = 0; j < 8; j++) { float d = v[j] - mean; s2 += d * d; }
    #pragma unroll
    for (int o = 16; o > 0; o >>= 1) s2 += __shfl_xor_sync(0xffffffffu, s2, o);
    float inv = rsqrtf(s2 * (1.f / EMBD) + 1e-5f);
    #pragma unroll
    for (int j = 0; j < 8; j++) {
        int c = lane + 32 * j;
        g_z[row * EMBD + c] += (v[j] - mean) * inv * gw[c] + bw[c];
    }
}

// ---------------- tensor-core flash attention ----------------
// block = 128 threads (4 warps), 64 q-rows per block (16 per warp), chunks of 64 kv.
#define FP 136
#define VP 72
#define FA2_SMEM ((4 * 64 * FP + 2 * 128 * VP) * 2)   // 106496 bytes

__global__ __launch_bounds__(128)
void flash2_kernel() {
    extern __shared__ __nv_bfloat16 fsm2[];
    __nv_bfloat16* Qh = fsm2;
    __nv_bfloat16* Ql = fsm2 + 64 * FP;
    __nv_bfloat16* Kh = fsm2 + 2 * 64 * FP;
    __nv_bfloat16* Vh = fsm2 + 4 * 64 * FP;
    __nv_bfloat16* Vl = fsm2 + 4 * 64 * FP + 128 * VP;

    int tid = threadIdx.x;
    int lane = tid & 31, w = tid >> 5;
    int g = lane >> 2, tig = lane & 3;
    int m0 = blockIdx.x * 64;
    int b = blockIdx.y >> 1, h = blockIdx.y & 1;

    const float* qb = g_qkv + (size_t)b * NTOK * 768 + h * DH;
    const float* kb = qb + 256;
    const float* vb = qb + 512;

    uint32_t sbase = smem_u32(fsm2);

    // Q tile -> smem (split)
    for (int i = tid; i < 2048; i += 128) {
        int r = i >> 5, c4 = (i & 31) * 4;
        int src = m0 + r; if (src > NTOK - 1) src = NTOK - 1;
        float4 v = *(const float4*)(qb + (size_t)src * 768 + c4);
        uint32_t h01, l01, h23, l23;
        split2(v.x, v.y, h01, l01);
        split2(v.z, v.w, h23, l23);
        *(uint2*)&Qh[r * FP + c4] = make_uint2(h01, h23);
        *(uint2*)&Ql[r * FP + c4] = make_uint2(l01, l23);
    }

    float oacc[16][4];
    #pragma unroll
    for (int i = 0; i < 16; i++)
        #pragma unroll
        for (int e = 0; e < 4; e++) oacc[i][e] = 0.f;
    float rm0 = -1e30f, rm1 = -1e30f, rl0 = 0.f, rl1 = 0.f;

    int a_row = (lane & 7) + ((lane >> 3) & 1) * 8;
    int a_col = ((lane >> 4) & 1) * 8;
    int b_row = (lane & 7) + ((lane >> 4) & 1) * 8;
    int b_col = ((lane >> 3) & 1) * 8;

    for (int nt = 0; nt < 7; nt++) {
        int n0c = nt * 64;
        __syncthreads();
        // K chunk (split, [seq][d])
        for (int i = tid; i < 2048; i += 128) {
            int r = i >> 5, c4 = (i & 31) * 4;
            int src = n0c + r; if (src > NTOK - 1) src = NTOK - 1;
            float4 v = *(const float4*)(kb + (size_t)src * 768 + c4);
            uint32_t h01, l01, h23, l23;
            split2(v.x, v.y, h01, l01);
            split2(v.z, v.w, h23, l23);
            *(uint2*)&Kh[r * FP + c4] = make_uint2(h01, h23);
            *(uint2*)&Kh[64 * FP + r * FP + c4] = make_uint2(l01, l23);
        }
        // V chunk transposed (split, [d][seq])
        for (int i = tid; i < 2048; i += 128) {
            int r = i & 63, cg = i >> 6;
            int src = n0c + r; if (src > NTOK - 1) src = NTOK - 1;
            float4 v = *(const float4*)(vb + (size_t)src * 768 + cg * 4);
            const float* vp = &v.x;
            #pragma unroll
            for (int j = 0; j < 4; j++) {
                __nv_bfloat16 h_, l_;
                split1(vp[j], h_, l_);
                Vh[(cg * 4 + j) * VP + r] = h_;
                Vl[(cg * 4 + j) * VP + r] = l_;
            }
        }
        __syncthreads();

        // S = Q K^T  (3-pass split)
        float sacc[8][4];
        #pragma unroll
        for (int nf = 0; nf < 8; nf++)
            #pragma unroll
            for (int e = 0; e < 4; e++) sacc[nf][e] = 0.f;

        #pragma unroll
        for (int ks = 0; ks < 8; ks++) {
            int k0 = ks * 16;
            uint32_t ah[4], al[4];
            uint32_t qad = sbase + ((w * 16 + a_row) * FP + k0 + a_col) * 2;
            ldsm4v(ah, qad);
            ldsm4v(al, qad + 64 * FP * 2);
            #pragma unroll
            for (int nt2 = 0; nt2 < 4; nt2++) {
                uint32_t kad = sbase + (2 * 64 * FP + (nt2 * 16 + b_row) * FP + k0 + b_col) * 2;
                uint32_t bh_[4], bl_[4];
                ldsm4v(bh_, kad);
                ldsm4v(bl_, kad + 64 * FP * 2);
                mma16816(sacc[nt2 * 2],     ah, &bh_[0]);
                mma16816(sacc[nt2 * 2],     ah, &bl_[0]);
                mma16816(sacc[nt2 * 2],     al, &bh_[0]);
                mma16816(sacc[nt2 * 2 + 1], ah, &bh_[2]);
                mma16816(sacc[nt2 * 2 + 1], ah, &bl_[2]);
                mma16816(sacc[nt2 * 2 + 1], al, &bh_[2]);
            }
        }

        // mask + online softmax
        float mx0 = -1e30f, mx1 = -1e30f;
        #pragma unroll
        for (int nf = 0; nf < 8; nf++) {
            int c0 = n0c + nf * 8 + 2 * tig;
            if (c0 >= NTOK)     { sacc[nf][0] = -1e30f; sacc[nf][2] = -1e30f; }
            if (c0 + 1 >= NTOK) { sacc[nf][1] = -1e30f; sacc[nf][3] = -1e30f; }
            mx0 = fmaxf(mx0, fmaxf(sacc[nf][0], sacc[nf][1]));
            mx1 = fmaxf(mx1, fmaxf(sacc[nf][2], sacc[nf][3]));
        }
        mx0 = fmaxf(mx0, __shfl_xor_sync(0xffffffffu, mx0, 1));
        mx0 = fmaxf(mx0, __shfl_xor_sync(0xffffffffu, mx0, 2));
        mx1 = fmaxf(mx1, __shfl_xor_sync(0xffffffffu, mx1, 1));
        mx1 = fmaxf(mx1, __shfl_xor_sync(0xffffffffu, mx1, 2));
        float nm0 = fmaxf(rm0, mx0), nm1 = fmaxf(rm1, mx1);
        float sc0 = fast_exp(rm0 - nm0), sc1 = fast_exp(rm1 - nm1);
        rm0 = nm0; rm1 = nm1;
        float rs0 = 0.f, rs1 = 0.f;
        uint32_t ph[8][2], pl[8][2];
        #pragma unroll
        for (int nf = 0; nf < 8; nf++) {
            float p0 = fast_exp(sacc[nf][0] - nm0);
            float p1 = fast_exp(sacc[nf][1] - nm0);
            float p2 = fast_exp(sacc[nf][2] - nm1);
            float p3 = fast_exp(sacc[nf][3] - nm1);
            rs0 += p0 + p1; rs1 += p2 + p3;
            split2(p0, p1, ph[nf][0], pl[nf][0]);
            split2(p2, p3, ph[nf][1], pl[nf][1]);
        }
        rs0 += __shfl_xor_sync(0xffffffffu, rs0, 1);
        rs0 += __shfl_xor_sync(0xffffffffu, rs0, 2);
        rs1 += __shfl_xor_sync(0xffffffffu, rs1, 1);
        rs1 += __shfl_xor_sync(0xffffffffu, rs1, 2);
        rl0 = rl0 * sc0 + rs0;
        rl1 = rl1 * sc1 + rs1;
        #pragma unroll
        for (int onf = 0; onf < 16; onf++) {
            oacc[onf][0] *= sc0; oacc[onf][1] *= sc0;
            oacc[onf][2] *= sc1; oacc[onf][3] *= sc1;
        }

        // O += P V  (P register-resident; 3-pass)
        #pragma unroll
        for (int ks = 0; ks < 4; ks++) {
            uint32_t ah[4] = {ph[2 * ks][0], ph[2 * ks][1], ph[2 * ks + 1][0], ph[2 * ks + 1][1]};
            uint32_t al[4] = {pl[2 * ks][0], pl[2 * ks][1], pl[2 * ks + 1][0], pl[2 * ks + 1][1]};
            #pragma unroll
            for (int dt = 0; dt < 8; dt++) {
                uint32_t vad = sbase + (4 * 64 * FP + (dt * 16 + b_row) * VP + ks * 16 + b_col) * 2;
                uint32_t bh_[4], bl_[4];
                ldsm4v(bh_, vad);
                ldsm4v(bl_, vad + 128 * VP * 2);
                mma16816(oacc[dt * 2],     ah, &bh_[0]);
                mma16816(oacc[dt * 2],     ah, &bl_[0]);
                mma16816(oacc[dt * 2],     al, &bh_[0]);
                mma16816(oacc[dt * 2 + 1], ah, &bh_[2]);
                mma16816(oacc[dt * 2 + 1], ah, &bl_[2]);
                mma16816(oacc[dt * 2 + 1], al, &bh_[2]);
            }
        }
    }

    // epilogue: divide by l*16, split-store to g_oh/g_ol
    float inv0 = 1.f / (rl0 * 16.f);
    float inv1 = 1.f / (rl1 * 16.f);
    int row0 = m0 + w * 16 + g, row1 = row0 + 8;
    #pragma unroll
    for (int onf = 0; onf < 16; onf++) {
        int col = h * DH + onf * 8 + 2 * tig;
        uint32_t hi, lo;
        if (row0 < NTOK) {
            split2(oacc[onf][0] * inv0, oacc[onf][1] * inv0, hi, lo);
            size_t off = ((size_t)b * NTOK + row0) * EMBD + col;
            *(uint32_t*)&g_oh[off] = hi;
            *(uint32_t*)&g_ol[off] = lo;
        }
        if (row1 < NTOK) {
            split2(oacc[onf][2] * inv1, oacc[onf][3] * inv1, hi, lo);
            size_t off = ((size_t)b * NTOK + row1) * EMBD + col;
            *(uint32_t*)&g_oh[off] = hi;
            *(uint32_t*)&g_ol[off] = lo;
        }
    }
}

// ---------------- head ----------------
__global__ void head_kernel(const float* __restrict__ lg, const float* __restrict__ lb,
                            const float* __restrict__ Wc, const float* __restrict__ bc,
                            float* __restrict__ out) {
    __shared__ float sh[8];
    int b = blockIdx.x;
    int c = threadIdx.x;
    const float* zb = g_z + (size_t)b * NTOK * EMBD;
    float s = 0.f;
    for (int n = 0; n < NTOK; n++) s += zb[(size_t)n * EMBD + c];
    float pooled = s * (1.f / NTOK);
    float mean = block_sum_256(pooled, sh) * (1.f / EMBD);
    float d = pooled - mean;
    float var = block_sum_256(d * d, sh) * (1.f / EMBD);
    float ln = d * rsqrtf(var + 1e-5f) * lg[c] + lb[c];
    float l0 = block_sum_256(ln * Wc[c * 2 + 0], sh);
    float l1 = block_sum_256(ln * Wc[c * 2 + 1], sh);
    if (c == 0) {
        l0 += bc[0];
        l1 += bc[1];
        float mx = fmaxf(l0, l1);
        float lse = mx + logf(expf(l0 - mx) + expf(l1 - mx));
        out[b * 2 + 0] = l0 - lse;
        out[b * 2 + 1] = l1 - lse;
    }
}

// ---------------- launch ----------------
extern "C" void kernel_launch(void* const* d_in, const int* in_sizes, int n_in,
                              void* d_out, int out_size) {
    const float* x    = (const float*)d_in[0];
    const float* W1   = (const float*)d_in[1];
    const float* b1   = (const float*)d_in[2];
    const float* cls1 = (const float*)d_in[3];
    const float* W2   = (const float*)d_in[4];
    const float* b2   = (const float*)d_in[5];
    const float* cls2 = (const float*)d_in[6];
    const float* ln1g = (const float*)d_in[7];
    const float* ln1b = (const float*)d_in[8];
    const float* Wq   = (const float*)d_in[9];
    const float* bq   = (const float*)d_in[10];
    const float* Wk   = (const float*)d_in[11];
    const float* bk   = (const float*)d_in[12];
    const float* Wv   = (const float*)d_in[13];
    const float* bv   = (const float*)d_in[14];
    const float* Wp   = (const float*)d_in[15];
    const float* bp   = (const float*)d_in[16];
    const float* ln2g = (const float*)d_in[17];
    const float* ln2b = (const float*)d_in[18];
    const float* lncg = (const float*)d_in[19];
    const float* lncb = (const float*)d_in[20];
    const float* Wc   = (const float*)d_in[21];
    const float* bc   = (const float*)d_in[22];
    float* out = (float*)d_out;

    __nv_bfloat16 *p1h, *p1l, *p2h, *p2l, *hh, *hl, *oh, *ol;
    __nv_bfloat16 *w1h, *w1l, *w2h, *w2l, *wqh, *wql, *wph, *wpl;
    float *e1, *e2, *qkvp, *op_, *bqkv;
    cudaGetSymbolAddress((void**)&p1h, g_p1h);
    cudaGetSymbolAddress((void**)&p1l, g_p1l);
    cudaGetSymbolAddress((void**)&p2h, g_p2h);
    cudaGetSymbolAddress((void**)&p2l, g_p2l);
    cudaGetSymbolAddress((void**)&hh, g_hh);
    cudaGetSymbolAddress((void**)&hl, g_hl);
    cudaGetSymbolAddress((void**)&oh, g_oh);
    cudaGetSymbolAddress((void**)&ol, g_ol);
    cudaGetSymbolAddress((void**)&w1h, g_w1h);
    cudaGetSymbolAddress((void**)&w1l, g_w1l);
    cudaGetSymbolAddress((void**)&w2h, g_w2h);
    cudaGetSymbolAddress((void**)&w2l, g_w2l);
    cudaGetSymbolAddress((void**)&wqh, g_wqh);
    cudaGetSymbolAddress((void**)&wql, g_wql);
    cudaGetSymbolAddress((void**)&wph, g_wph);
    cudaGetSymbolAddress((void**)&wpl, g_wpl);
    cudaGetSymbolAddress((void**)&e1, g_emb1);
    cudaGetSymbolAddress((void**)&e2, g_emb2);
    cudaGetSymbolAddress((void**)&qkvp, g_qkv);
    cudaGetSymbolAddress((void**)&op_, g_op);
    cudaGetSymbolAddress((void**)&bqkv, g_bqkv);

    cudaFuncSetAttribute(gemm_mma2, cudaFuncAttributeMaxDynamicSharedMemorySize, GEMM2_SMEM);
    cudaFuncSetAttribute(flash2_kernel, cudaFuncAttributeMaxDynamicSharedMemorySize, FA2_SMEM);

    // producers (split at source)
    im2row1_kernel<<<(ROWS_E * K1) / 256, 256>>>(x);
    im2row2_kernel<<<(ROWS_E * K2) / 256, 256>>>(x);
    wsplit_kernel<<<(256 * 768 + 255) / 256, 256>>>(W1, w1h, w1l, K1, EMBD);
    wsplit_kernel<<<(256 * 192 + 255) / 256, 256>>>(W2, w2h, w2l, K2, EMBD);
    wsplit_kernel<<<(256 * 256 + 255) / 256, 256>>>(Wp, wph, wpl, EMBD, EMBD);
    wqkv_split<<<(768 * 256) / 256, 256>>>(Wq, Wk, Wv, bq, bk, bv);

    // patch embeds
    gemm_mma2<<<dim3(2, ROWS_E / 128), 256, GEMM2_SMEM>>>(p1h, p1l, w1h, w1l, nullptr, e1, ROWS_E, EMBD, K1);
    gemm_mma2<<<dim3(2, ROWS_E / 128), 256, GEMM2_SMEM>>>(p2h, p2l, w2h, w2l, nullptr, e2, ROWS_E, EMBD, K2);

    assemble_kernel<<<dim3(NTOK, BATCH), 256>>>(b1, cls1, b2, cls2);
    ln_kernel<<<ROWS_T / 8, 256>>>(ln1g, ln1b);

    // fused QKV
    gemm_mma2<<<dim3(6, ROWS_T / 128), 256, GEMM2_SMEM>>>(hh, hl, wqh, wql, bqkv, qkvp, ROWS_T, 768, EMBD);

    // flash attention (tensor cores)
    flash2_kernel<<<dim3(7, BATCH * HEADS), 128, FA2_SMEM>>>();

    // output projection
    gemm_mma2<<<dim3(2, ROWS_T / 128), 256, GEMM2_SMEM>>>(oh, ol, wph, wpl, bp, op_, ROWS_T, EMBD, EMBD);

    ln_res_kernel<<<ROWS_T / 8, 256>>>(ln2g, ln2b);
    head_kernel<<<BATCH, 256>>>(lncg, lncb, Wc, bc, out);
}

// round 10
// speedup vs baseline: 3.2630x; 1.1650x over previous
#include <cuda_runtime.h>
#include <cuda_bf16.h>
#include <cstdint>
#include <math.h>

// ---------------- problem constants ----------------
#define BATCH   128
#define NTOK    394
#define EMBD    256
#define NP      196
#define HEADS   2
#define DH      128
#define K1      768
#define K2      192
#define ROWS_E  (BATCH*NP)         // 25088
#define ROWS_T  (BATCH*NTOK)       // 50432

// ---------------- scratch ----------------
__device__ __nv_bfloat16 g_p1h[(size_t)ROWS_E * K1];
__device__ __nv_bfloat16 g_p1l[(size_t)ROWS_E * K1];
__device__ __nv_bfloat16 g_p2h[(size_t)ROWS_E * K2];
__device__ __nv_bfloat16 g_p2l[(size_t)ROWS_E * K2];
__device__ __nv_bfloat16 g_hh [(size_t)ROWS_T * EMBD];
__device__ __nv_bfloat16 g_hl [(size_t)ROWS_T * EMBD];
__device__ __nv_bfloat16 g_oh [(size_t)ROWS_T * EMBD];
__device__ __nv_bfloat16 g_ol [(size_t)ROWS_T * EMBD];
__device__ __nv_bfloat16 g_qkvh[(size_t)ROWS_T * 768];
__device__ __nv_bfloat16 g_qkvl[(size_t)ROWS_T * 768];
__device__ __nv_bfloat16 g_w1h[256 * 768], g_w1l[256 * 768];
__device__ __nv_bfloat16 g_w2h[256 * 192], g_w2l[256 * 192];
__device__ __nv_bfloat16 g_wqh[768 * 256], g_wql[768 * 256];
__device__ __nv_bfloat16 g_wph[256 * 256], g_wpl[256 * 256];
__device__ float g_bqkv[768];
__device__ float g_emb1[(size_t)ROWS_E * EMBD];
__device__ float g_emb2[(size_t)ROWS_E * EMBD];
__device__ float g_z   [(size_t)ROWS_T * EMBD];
__device__ float g_op  [(size_t)ROWS_T * EMBD];

// ---------------- helpers ----------------
__device__ __forceinline__ uint32_t smem_u32(const void* p) {
    return (uint32_t)__cvta_generic_to_shared(p);
}

__device__ __forceinline__ void split2(float x, float y, uint32_t& hi, uint32_t& lo) {
    asm("cvt.rn.bf16x2.f32 %0, %1, %2;" : "=r"(hi) : "f"(y), "f"(x));
    float hx = __uint_as_float(hi << 16);
    float hy = __uint_as_float(hi & 0xffff0000u);
    float lx = x - hx, ly = y - hy;
    asm("cvt.rn.bf16x2.f32 %0, %1, %2;" : "=r"(lo) : "f"(ly), "f"(lx));
}

__device__ __forceinline__ void split1(float v, __nv_bfloat16& hi, __nv_bfloat16& lo) {
    hi = __float2bfloat16(v);
    lo = __float2bfloat16(v - __bfloat162float(hi));
}

__device__ __forceinline__ void mma16816(float* c, const uint32_t* a, const uint32_t* b) {
    asm volatile("mma.sync.aligned.m16n8k16.row.col.f32.bf16.bf16.f32 "
                 "{%0,%1,%2,%3}, {%4,%5,%6,%7}, {%8,%9}, {%0,%1,%2,%3};"
                 : "+f"(c[0]), "+f"(c[1]), "+f"(c[2]), "+f"(c[3])
                 : "r"(a[0]), "r"(a[1]), "r"(a[2]), "r"(a[3]), "r"(b[0]), "r"(b[1]));
}

__device__ __forceinline__ void ldsm4v(uint32_t* r, uint32_t addr) {
    asm volatile("ldmatrix.sync.aligned.m8n8.x4.shared.b16 {%0,%1,%2,%3}, [%4];"
        : "=r"(r[0]), "=r"(r[1]), "=r"(r[2]), "=r"(r[3]) : "r"(addr));
}

__device__ __forceinline__ void ldsm4t(uint32_t* r, uint32_t addr) {
    asm volatile("ldmatrix.sync.aligned.m8n8.x4.trans.shared.b16 {%0,%1,%2,%3}, [%4];"
        : "=r"(r[0]), "=r"(r[1]), "=r"(r[2]), "=r"(r[3]) : "r"(addr));
}

__device__ __forceinline__ void cp16(uint32_t smem, const void* gmem) {
    asm volatile("cp.async.ca.shared.global [%0], [%1], 16;" :: "r"(smem), "l"(gmem));
}
__device__ __forceinline__ void cp_commit() {
    asm volatile("cp.async.commit_group;" ::: "memory");
}
__device__ __forceinline__ void cp_wait1() {
    asm volatile("cp.async.wait_group 1;" ::: "memory");
}
__device__ __forceinline__ void cp_wait0() {
    asm volatile("cp.async.wait_group 0;" ::: "memory");
}

// exp on the FMA pipe; valid for x <= 0
__device__ __forceinline__ float fast_exp(float x) {
    float y = x * 1.4426950408889634f;
    float n = rintf(y);
    float f = y - n;
    float p = 1.3333558146e-3f;
    p = fmaf(p, f, 9.6181291076e-3f);
    p = fmaf(p, f, 5.5504108664e-2f);
    p = fmaf(p, f, 2.4022650696e-1f);
    p = fmaf(p, f, 6.9314718056e-1f);
    p = fmaf(p, f, 1.0f);
    int e = (int)n;
    float r = __int_as_float((uint32_t)(e + 127) << 23) * p;
    return (n < -125.f) ? 0.f : r;
}

__device__ __forceinline__ float block_sum_256(float v, float* sh) {
    #pragma unroll
    for (int o = 16; o > 0; o >>= 1) v += __shfl_xor_sync(0xffffffffu, v, o);
    __syncthreads();
    if ((threadIdx.x & 31) == 0) sh[threadIdx.x >> 5] = v;
    __syncthreads();
    float r = 0.f;
    #pragma unroll
    for (int i = 0; i < 8; i++) r += sh[i];
    return r;
}

// ---------------- im2row (writes split bf16) ----------------
__global__ void im2row1_kernel(const float* __restrict__ x) {
    int idx = blockIdx.x * 256 + threadIdx.x;
    int f = idx % K1;
    int r = idx / K1;
    int b = r / NP, i = r % NP;
    int hi = i / 14, wi = i % 14;
    int pr = f / 48; int rem = f % 48; int pc = rem / 3; int c = rem % 3;
    float val = x[(((size_t)b * 3 + c) * 224 + (hi * 16 + pr)) * 224 + (wi * 16 + pc)];
    __nv_bfloat16 h_, l_;
    split1(val, h_, l_);
    g_p1h[idx] = h_; g_p1l[idx] = l_;
}

__global__ void im2row2_kernel(const float* __restrict__ x) {
    int idx = blockIdx.x * 256 + threadIdx.x;
    int f = idx % K2;
    int r = idx / K2;
    int b = r / NP, j = r % NP;
    int m = 4 * j + 3;
    int hi = m / 28, wi = m % 28;
    int pr = f / 24; int rem = f % 24; int pc = rem / 3; int c = rem % 3;
    float val = x[(((size_t)b * 3 + c) * 224 + (hi * 8 + pr)) * 224 + (wi * 8 + pc)];
    __nv_bfloat16 h_, l_;
    split1(val, h_, l_);
    g_p2h[idx] = h_; g_p2l[idx] = l_;
}

// ---------------- weight prep ----------------
__global__ void wsplit_kernel(const float* __restrict__ W, __nv_bfloat16* __restrict__ oh,
                              __nv_bfloat16* __restrict__ ol, int Kd, int Nd) {
    int idx = blockIdx.x * 256 + threadIdx.x;
    if (idx >= Kd * Nd) return;
    int n = idx / Kd, k = idx % Kd;
    __nv_bfloat16 h_, l_;
    split1(W[k * Nd + n], h_, l_);
    oh[idx] = h_; ol[idx] = l_;
}

__global__ void wqkv_split(const float* __restrict__ Wq, const float* __restrict__ Wk,
                           const float* __restrict__ Wv, const float* __restrict__ bq,
                           const float* __restrict__ bk, const float* __restrict__ bv) {
    int idx = blockIdx.x * 256 + threadIdx.x;   // 768*256
    int n = idx >> 8, k = idx & 255;
    const float* src = (n < 256) ? Wq : ((n < 512) ? Wk : Wv);
    __nv_bfloat16 h_, l_;
    split1(src[k * 256 + (n & 255)], h_, l_);
    g_wqh[idx] = h_; g_wql[idx] = l_;
    if (idx < 768) g_bqkv[idx] = ((idx < 256) ? bq : ((idx < 512) ? bk : bv))[idx & 255];
}

// ---------------- bf16 tensor-core GEMM, operands pre-split ----------------
#define GAP  40
#define GSTG (4 * 128 * GAP)
#define GEMM2_SMEM (2 * GSTG * 2)

__global__ __launch_bounds__(256)
void gemm_mma2(const __nv_bfloat16* __restrict__ Ah, const __nv_bfloat16* __restrict__ Al,
               const __nv_bfloat16* __restrict__ Bh, const __nv_bfloat16* __restrict__ Bl,
               const float* __restrict__ bias, float* __restrict__ C,
               __nv_bfloat16* __restrict__ Ch, __nv_bfloat16* __restrict__ Cl,
               int M, int N, int K) {
    extern __shared__ __nv_bfloat16 gsm[];
    uint32_t sbase = smem_u32(gsm);
    int t = threadIdx.x, lane = t & 31, w = t >> 5;
    int g = lane >> 2, tig = lane & 3;
    int wm = (w & 1) * 64, wn = (w >> 1) * 32;
    int m0 = blockIdx.y * 128, n0 = blockIdx.x * 128;
    const __nv_bfloat16* Abh = Ah + (size_t)m0 * K;
    const __nv_bfloat16* Abl = Al + (size_t)m0 * K;
    const __nv_bfloat16* Bbh = Bh + (size_t)n0 * K;
    const __nv_bfloat16* Bbl = Bl + (size_t)n0 * K;

    int a_row = (lane & 7) + ((lane >> 3) & 1) * 8;
    int a_col = ((lane >> 4) & 1) * 8;
    int b_row = (lane & 7) + ((lane >> 4) & 1) * 8;
    int b_col = ((lane >> 3) & 1) * 8;

    uint4 pA[2], pAl[2], pB[2], pBl[2];

    #pragma unroll
    for (int j = 0; j < 2; j++) {
        int i = t + 256 * j;
        int r = i >> 2, c8 = (i & 3) * 8;
        pA[j]  = *(const uint4*)(Abh + (size_t)r * K + c8);
        pAl[j] = *(const uint4*)(Abl + (size_t)r * K + c8);
        pB[j]  = *(const uint4*)(Bbh + (size_t)r * K + c8);
        pBl[j] = *(const uint4*)(Bbl + (size_t)r * K + c8);
    }
    #pragma unroll
    for (int j = 0; j < 2; j++) {
        int i = t + 256 * j;
        int r = i >> 2, c8 = (i & 3) * 8;
        *(uint4*)(gsm + (size_t)r * GAP + c8)                 = pA[j];
        *(uint4*)(gsm + 128 * GAP + (size_t)r * GAP + c8)     = pAl[j];
        *(uint4*)(gsm + 2 * 128 * GAP + (size_t)r * GAP + c8) = pB[j];
        *(uint4*)(gsm + 3 * 128 * GAP + (size_t)r * GAP + c8) = pBl[j];
    }
    __syncthreads();

    float acc[4][4][4];
    #pragma unroll
    for (int mt = 0; mt < 4; mt++)
        #pragma unroll
        for (int nf = 0; nf < 4; nf++)
            #pragma unroll
            for (int e = 0; e < 4; e++) acc[mt][nf][e] = 0.f;

    int kt = K >> 5;
    for (int tt = 0; tt < kt; tt++) {
        int cur = tt & 1;
        if (tt + 1 < kt) {
            int kb = (tt + 1) * 32;
            #pragma unroll
            for (int j = 0; j < 2; j++) {
                int i = t + 256 * j;
                int r = i >> 2, c8 = (i & 3) * 8;
                pA[j]  = *(const uint4*)(Abh + (size_t)r * K + kb + c8);
                pAl[j] = *(const uint4*)(Abl + (size_t)r * K + kb + c8);
                pB[j]  = *(const uint4*)(Bbh + (size_t)r * K + kb + c8);
                pBl[j] = *(const uint4*)(Bbl + (size_t)r * K + kb + c8);
            }
        }
        uint32_t sA = sbase + cur * GSTG * 2;
        #pragma unroll
        for (int ks = 0; ks < 32; ks += 16) {
            uint32_t ah4[4][4], al4[4][4];
            #pragma unroll
            for (int mt = 0; mt < 4; mt++) {
                uint32_t ad = sA + ((wm + mt * 16 + a_row) * GAP + ks + a_col) * 2;
                ldsm4v(ah4[mt], ad);
                ldsm4v(al4[mt], ad + 128 * GAP * 2);
            }
            uint32_t bh4[2][4], bl4[2][4];
            #pragma unroll
            for (int nt2 = 0; nt2 < 2; nt2++) {
                uint32_t bd = sA + (2 * 128 * GAP + (wn + nt2 * 16 + b_row) * GAP + ks + b_col) * 2;
                ldsm4v(bh4[nt2], bd);
                ldsm4v(bl4[nt2], bd + 128 * GAP * 2);
            }
            #pragma unroll
            for (int mt = 0; mt < 4; mt++)
                #pragma unroll
                for (int nf = 0; nf < 4; nf++) {
                    uint32_t* bhp = &bh4[nf >> 1][(nf & 1) * 2];
                    uint32_t* blp = &bl4[nf >> 1][(nf & 1) * 2];
                    mma16816(acc[mt][nf], ah4[mt], bhp);
                    mma16816(acc[mt][nf], ah4[mt], blp);
                    mma16816(acc[mt][nf], al4[mt], bhp);
                }
        }
        if (tt + 1 < kt) {
            __nv_bfloat16* nb = gsm + ((tt + 1) & 1) * GSTG;
            #pragma unroll
            for (int j = 0; j < 2; j++) {
                int i = t + 256 * j;
                int r = i >> 2, c8 = (i & 3) * 8;
                *(uint4*)(nb + (size_t)r * GAP + c8)                 = pA[j];
                *(uint4*)(nb + 128 * GAP + (size_t)r * GAP + c8)     = pAl[j];
                *(uint4*)(nb + 2 * 128 * GAP + (size_t)r * GAP + c8) = pB[j];
                *(uint4*)(nb + 3 * 128 * GAP + (size_t)r * GAP + c8) = pBl[j];
            }
        }
        __syncthreads();
    }

    #pragma unroll
    for (int mt = 0; mt < 4; mt++) {
        int r0 = m0 + wm + mt * 16 + g;
        #pragma unroll
        for (int nf = 0; nf < 4; nf++) {
            int c0 = n0 + wn + nf * 8 + 2 * tig;
            float2 v0, v1;
            v0.x = acc[mt][nf][0]; v0.y = acc[mt][nf][1];
            v1.x = acc[mt][nf][2]; v1.y = acc[mt][nf][3];
            if (bias) {
                float2 bb = *(const float2*)(bias + c0);
                v0.x += bb.x; v0.y += bb.y;
                v1.x += bb.x; v1.y += bb.y;
            }
            if (Ch) {
                uint32_t hh_, ll_;
                split2(v0.x, v0.y, hh_, ll_);
                *(uint32_t*)&Ch[(size_t)r0 * N + c0] = hh_;
                *(uint32_t*)&Cl[(size_t)r0 * N + c0] = ll_;
                split2(v1.x, v1.y, hh_, ll_);
                *(uint32_t*)&Ch[(size_t)(r0 + 8) * N + c0] = hh_;
                *(uint32_t*)&Cl[(size_t)(r0 + 8) * N + c0] = ll_;
            } else {
                *(float2*)(C + (size_t)r0 * N + c0) = v0;
                *(float2*)(C + (size_t)(r0 + 8) * N + c0) = v1;
            }
        }
    }
}

// ---------------- fused assemble + LN1: z = concat(p2r,p1); h = LN(z) split ----------------
__global__ void ln_fused_kernel(const float* __restrict__ gw, const float* __restrict__ bw,
                                const float* __restrict__ b1, const float* __restrict__ cls1,
                                const float* __restrict__ b2, const float* __restrict__ cls2) {
    int wid = threadIdx.x >> 5, lane = threadIdx.x & 31;
    long long row = (long long)blockIdx.x * 8 + wid;
    if (row >= ROWS_T) return;
    int b = (int)(row / NTOK), n = (int)(row % NTOK);

    const float* src; const float* badd = nullptr;
    if (n == 0)           { src = cls2; }
    else if (n <= NP)     { src = g_emb2 + ((size_t)(b * NP + (n - 1))) * EMBD; badd = b2; }
    else if (n == NP + 1) { src = cls1; }
    else                  { src = g_emb1 + ((size_t)(b * NP + (n - NP - 2))) * EMBD; badd = b1; }

    float v[8];
    float s = 0.f;
    #pragma unroll
    for (int j = 0; j < 8; j++) {
        int c = lane + 32 * j;
        v[j] = src[c] + (badd ? badd[c] : 0.f);
        s += v[j];
    }
    #pragma unroll
    for (int o = 16; o > 0; o >>= 1) s += __shfl_xor_sync(0xffffffffu, s, o);
    float mean = s * (1.f / EMBD);
    float s2 = 0.f;
    #pragma unroll
    for (int j = 0; j < 8; j++) { float d = v[j] - mean; s2 += d * d; }
    #pragma unroll
    for (int o = 16; o > 0; o >>= 1) s2 += __shfl_xor_sync(0xffffffffu, s2, o);
    float inv = rsqrtf(s2 * (1.f / EMBD) + 1e-5f);
    #pragma unroll
    for (int j = 0; j < 8; j++) {
        int c = lane + 32 * j;
        g_z[row * EMBD + c] = v[j];
        float o = (v[j] - mean) * inv * gw[c] + bw[c];
        __nv_bfloat16 h_, l_;
        split1(o, h_, l_);
        g_hh[row * EMBD + c] = h_;
        g_hl[row * EMBD + c] = l_;
    }
}

// z += LN(op)
__global__ void ln_res_kernel(const float* __restrict__ gw, const float* __restrict__ bw) {
    int wid = threadIdx.x >> 5, lane = threadIdx.x & 31;
    long long row = (long long)blockIdx.x * 8 + wid;
    if (row >= ROWS_T) return;
    const float* p = g_op + row * EMBD;
    float v[8];
    float s = 0.f;
    #pragma unroll
    for (int j = 0; j < 8; j++) { v[j] = p[lane + 32 * j]; s += v[j]; }
    #pragma unroll
    for (int o = 16; o > 0; o >>= 1) s += __shfl_xor_sync(0xffffffffu, s, o);
    float mean = s * (1.f / EMBD);
    float s2 = 0.f;
    #pragma unroll
    for (int j = 0; j < 8; j++) { float d = v[j] - mean; s2 += d * d; }
    #pragma unroll
    for (int o = 16; o > 0; o >>= 1) s2 += __shfl_xor_sync(0xffffffffu, s2, o);
    float inv = rsqrtf(s2 * (1.f / EMBD) + 1e-5f);
    #pragma unroll
    for (int j = 0; j < 8; j++) {
        int c = lane + 32 * j;
        g_z[row * EMBD + c] += (v[j] - mean) * inv * gw[c] + bw[c];
    }
}

// ---------------- tensor-core flash attention v3 ----------------
// pre-split QKV input, cp.async double-buffered K/V, ldmatrix.trans for V.
#define FP 136
#define KVSTG (4 * 64 * FP)                        // one K/V stage (Kh,Kl,Vh,Vl)
#define FA3_SMEM ((2 * 64 * FP + 2 * KVSTG) * 2)   // 174080 bytes

__global__ __launch_bounds__(128)
void flash3_kernel() {
    extern __shared__ __nv_bfloat16 fsm3[];
    uint32_t sbase = smem_u32(fsm3);

    int tid = threadIdx.x;
    int lane = tid & 31, w = tid >> 5;
    int g = lane >> 2, tig = lane & 3;
    int m0 = blockIdx.x * 64;
    int b = blockIdx.y >> 1, h = blockIdx.y & 1;

    size_t rowbase = (size_t)b * NTOK * 768;
    const __nv_bfloat16* qh_g = g_qkvh + rowbase + h * DH;
    const __nv_bfloat16* ql_g = g_qkvl + rowbase + h * DH;
    const __nv_bfloat16* kh_g = qh_g + 256;
    const __nv_bfloat16* kl_g = ql_g + 256;
    const __nv_bfloat16* vh_g = qh_g + 512;
    const __nv_bfloat16* vl_g = ql_g + 512;

    uint32_t Qh_s = sbase;
    uint32_t Ql_s = sbase + 64 * FP * 2;
    uint32_t KV_s = sbase + 2 * 64 * FP * 2;

    // group 0: Q tile + K/V chunk 0
    for (int i = tid; i < 1024; i += 128) {
        int r = i >> 4, c8 = (i & 15) * 8;
        int src = m0 + r; if (src > NTOK - 1) src = NTOK - 1;
        cp16(Qh_s + (r * FP + c8) * 2, qh_g + (size_t)src * 768 + c8);
        cp16(Ql_s + (r * FP + c8) * 2, ql_g + (size_t)src * 768 + c8);
    }
    {
        uint32_t st0 = KV_s;
        for (int i = tid; i < 1024; i += 128) {
            int r = i >> 4, c8 = (i & 15) * 8;
            int src = r; if (src > NTOK - 1) src = NTOK - 1;
            cp16(st0 + (r * FP + c8) * 2,                  kh_g + (size_t)src * 768 + c8);
            cp16(st0 + (64 * FP + r * FP + c8) * 2,        kl_g + (size_t)src * 768 + c8);
            cp16(st0 + (2 * 64 * FP + r * FP + c8) * 2,    vh_g + (size_t)src * 768 + c8);
            cp16(st0 + (3 * 64 * FP + r * FP + c8) * 2,    vl_g + (size_t)src * 768 + c8);
        }
    }
    cp_commit();

    float oacc[16][4];
    #pragma unroll
    for (int i = 0; i < 16; i++)
        #pragma unroll
        for (int e = 0; e < 4; e++) oacc[i][e] = 0.f;
    float rm0 = -1e30f, rm1 = -1e30f, rl0 = 0.f, rl1 = 0.f;

    int a_row = (lane & 7) + ((lane >> 3) & 1) * 8;
    int a_col = ((lane >> 4) & 1) * 8;
    int b_row = (lane & 7) + ((lane >> 4) & 1) * 8;
    int b_col = ((lane >> 3) & 1) * 8;

    for (int nt = 0; nt < 7; nt++) {
        if (nt < 6) {
            int n0n = (nt + 1) * 64;
            uint32_t stn = KV_s + ((nt + 1) & 1) * KVSTG * 2;
            for (int i = tid; i < 1024; i += 128) {
                int r = i >> 4, c8 = (i & 15) * 8;
                int src = n0n + r; if (src > NTOK - 1) src = NTOK - 1;
                cp16(stn + (r * FP + c8) * 2,               kh_g + (size_t)src * 768 + c8);
                cp16(stn + (64 * FP + r * FP + c8) * 2,     kl_g + (size_t)src * 768 + c8);
                cp16(stn + (2 * 64 * FP + r * FP + c8) * 2, vh_g + (size_t)src * 768 + c8);
                cp16(stn + (3 * 64 * FP + r * FP + c8) * 2, vl_g + (size_t)src * 768 + c8);
            }
            cp_commit();
            cp_wait1();
        } else {
            cp_wait0();
        }
        __syncthreads();

        int n0c = nt * 64;
        uint32_t stc = KV_s + (nt & 1) * KVSTG * 2;

        // S = Q K^T (3-pass split)
        float sacc[8][4];
        #pragma unroll
        for (int nf = 0; nf < 8; nf++)
            #pragma unroll
            for (int e = 0; e < 4; e++) sacc[nf][e] = 0.f;

        #pragma unroll
        for (int ks = 0; ks < 8; ks++) {
            int k0 = ks * 16;
            uint32_t ah[4], al[4];
            uint32_t qad = Qh_s + ((w * 16 + a_row) * FP + k0 + a_col) * 2;
            ldsm4v(ah, qad);
            ldsm4v(al, qad + 64 * FP * 2);
            #pragma unroll
            for (int nt2 = 0; nt2 < 4; nt2++) {
                uint32_t kad = stc + ((nt2 * 16 + b_row) * FP + k0 + b_col) * 2;
                uint32_t bh_[4], bl_[4];
                ldsm4v(bh_, kad);
                ldsm4v(bl_, kad + 64 * FP * 2);
                mma16816(sacc[nt2 * 2],     ah, &bh_[0]);
                mma16816(sacc[nt2 * 2],     ah, &bl_[0]);
                mma16816(sacc[nt2 * 2],     al, &bh_[0]);
                mma16816(sacc[nt2 * 2 + 1], ah, &bh_[2]);
                mma16816(sacc[nt2 * 2 + 1], ah, &bl_[2]);
                mma16816(sacc[nt2 * 2 + 1], al, &bh_[2]);
            }
        }

        // mask + online softmax
        float mx0 = -1e30f, mx1 = -1e30f;
        #pragma unroll
        for (int nf = 0; nf < 8; nf++) {
            int c0 = n0c + nf * 8 + 2 * tig;
            if (c0 >= NTOK)     { sacc[nf][0] = -1e30f; sacc[nf][2] = -1e30f; }
            if (c0 + 1 >= NTOK) { sacc[nf][1] = -1e30f; sacc[nf][3] = -1e30f; }
            mx0 = fmaxf(mx0, fmaxf(sacc[nf][0], sacc[nf][1]));
            mx1 = fmaxf(mx1, fmaxf(sacc[nf][2], sacc[nf][3]));
        }
        mx0 = fmaxf(mx0, __shfl_xor_sync(0xffffffffu, mx0, 1));
        mx0 = fmaxf(mx0, __shfl_xor_sync(0xffffffffu, mx0, 2));
        mx1 = fmaxf(mx1, __shfl_xor_sync(0xffffffffu, mx1, 1));
        mx1 = fmaxf(mx1, __shfl_xor_sync(0xffffffffu, mx1, 2));
        float nm0 = fmaxf(rm0, mx0), nm1 = fmaxf(rm1, mx1);
        float sc0 = fast_exp(rm0 - nm0), sc1 = fast_exp(rm1 - nm1);
        rm0 = nm0; rm1 = nm1;
        float rs0 = 0.f, rs1 = 0.f;
        uint32_t ph[8][2], pl[8][2];
        #pragma unroll
        for (int nf = 0; nf < 8; nf++) {
            float p0 = fast_exp(sacc[nf][0] - nm0);
            float p1 = fast_exp(sacc[nf][1] - nm0);
            float p2 = fast_exp(sacc[nf][2] - nm1);
            float p3 = fast_exp(sacc[nf][3] - nm1);
            rs0 += p0 + p1; rs1 += p2 + p3;
            split2(p0, p1, ph[nf][0], pl[nf][0]);
            split2(p2, p3, ph[nf][1], pl[nf][1]);
        }
        rs0 += __shfl_xor_sync(0xffffffffu, rs0, 1);
        rs0 += __shfl_xor_sync(0xffffffffu, rs0, 2);
        rs1 += __shfl_xor_sync(0xffffffffu, rs1, 1);
        rs1 += __shfl_xor_sync(0xffffffffu, rs1, 2);
        rl0 = rl0 * sc0 + rs0;
        rl1 = rl1 * sc1 + rs1;
        #pragma unroll
        for (int onf = 0; onf < 16; onf++) {
            oacc[onf][0] *= sc0; oacc[onf][1] *= sc0;
            oacc[onf][2] *= sc1; oacc[onf][3] *= sc1;
        }

        // O += P V  (P register-resident; V via ldmatrix.trans from [seq][d])
        uint32_t vbase = stc + 2 * 64 * FP * 2;
        #pragma unroll
        for (int ks = 0; ks < 4; ks++) {
            uint32_t ah[4] = {ph[2 * ks][0], ph[2 * ks][1], ph[2 * ks + 1][0], ph[2 * ks + 1][1]};
            uint32_t al[4] = {pl[2 * ks][0], pl[2 * ks][1], pl[2 * ks + 1][0], pl[2 * ks + 1][1]};
            #pragma unroll
            for (int dt = 0; dt < 8; dt++) {
                uint32_t vad = vbase + ((ks * 16 + a_row) * FP + dt * 16 + a_col) * 2;
                uint32_t bh_[4], bl_[4];
                ldsm4t(bh_, vad);
                ldsm4t(bl_, vad + 64 * FP * 2);
                mma16816(oacc[dt * 2],     ah, &bh_[0]);
                mma16816(oacc[dt * 2],     ah, &bl_[0]);
                mma16816(oacc[dt * 2],     al, &bh_[0]);
                mma16816(oacc[dt * 2 + 1], ah, &bh_[2]);
                mma16816(oacc[dt * 2 + 1], ah, &bl_[2]);
                mma16816(oacc[dt * 2 + 1], al, &bh_[2]);
            }
        }
        __syncthreads();
    }

    // epilogue
    float inv0 = 1.f / (rl0 * 16.f);
    float inv1 = 1.f / (rl1 * 16.f);
    int row0 = m0 + w * 16 + g, row1 = row0 + 8;
    #pragma unroll
    for (int onf = 0; onf < 16; onf++) {
        int col = h * DH + onf * 8 + 2 * tig;
        uint32_t hi, lo;
        if (row0 < NTOK) {
            split2(oacc[onf][0] * inv0, oacc[onf][1] * inv0, hi, lo);
            size_t off = ((size_t)b * NTOK + row0) * EMBD + col;
            *(uint32_t*)&g_oh[off] = hi;
            *(uint32_t*)&g_ol[off] = lo;
        }
        if (row1 < NTOK) {
            split2(oacc[onf][2] * inv1, oacc[onf][3] * inv1, hi, lo);
            size_t off = ((size_t)b * NTOK + row1) * EMBD + col;
            *(uint32_t*)&g_oh[off] = hi;
            *(uint32_t*)&g_ol[off] = lo;
        }
    }
}

// ---------------- head ----------------
__global__ void head_kernel(const float* __restrict__ lg, const float* __restrict__ lb,
                            const float* __restrict__ Wc, const float* __restrict__ bc,
                            float* __restrict__ out) {
    __shared__ float sh[8];
    int b = blockIdx.x;
    int c = threadIdx.x;
    const float* zb = g_z + (size_t)b * NTOK * EMBD;
    float s = 0.f;
    #pragma unroll 8
    for (int n = 0; n < NTOK; n++) s += zb[(size_t)n * EMBD + c];
    float pooled = s * (1.f / NTOK);
    float mean = block_sum_256(pooled, sh) * (1.f / EMBD);
    float d = pooled - mean;
    float var = block_sum_256(d * d, sh) * (1.f / EMBD);
    float ln = d * rsqrtf(var + 1e-5f) * lg[c] + lb[c];
    float l0 = block_sum_256(ln * Wc[c * 2 + 0], sh);
    float l1 = block_sum_256(ln * Wc[c * 2 + 1], sh);
    if (c == 0) {
        l0 += bc[0];
        l1 += bc[1];
        float mx = fmaxf(l0, l1);
        float lse = mx + logf(expf(l0 - mx) + expf(l1 - mx));
        out[b * 2 + 0] = l0 - lse;
        out[b * 2 + 1] = l1 - lse;
    }
}

// ---------------- launch ----------------
extern "C" void kernel_launch(void* const* d_in, const int* in_sizes, int n_in,
                              void* d_out, int out_size) {
    const float* x    = (const float*)d_in[0];
    const float* W1   = (const float*)d_in[1];
    const float* b1   = (const float*)d_in[2];
    const float* cls1 = (const float*)d_in[3];
    const float* W2   = (const float*)d_in[4];
    const float* b2   = (const float*)d_in[5];
    const float* cls2 = (const float*)d_in[6];
    const float* ln1g = (const float*)d_in[7];
    const float* ln1b = (const float*)d_in[8];
    const float* Wq   = (const float*)d_in[9];
    const float* bq   = (const float*)d_in[10];
    const float* Wk   = (const float*)d_in[11];
    const float* bk   = (const float*)d_in[12];
    const float* Wv   = (const float*)d_in[13];
    const float* bv   = (const float*)d_in[14];
    const float* Wp   = (const float*)d_in[15];
    const float* bp   = (const float*)d_in[16];
    const float* ln2g = (const float*)d_in[17];
    const float* ln2b = (const float*)d_in[18];
    const float* lncg = (const float*)d_in[19];
    const float* lncb = (const float*)d_in[20];
    const float* Wc   = (const float*)d_in[21];
    const float* bc   = (const float*)d_in[22];
    float* out = (float*)d_out;

    __nv_bfloat16 *p1h, *p1l, *p2h, *p2l, *hh, *hl, *oh, *ol, *qh, *ql;
    __nv_bfloat16 *w1h, *w1l, *w2h, *w2l, *wqh, *wql, *wph, *wpl;
    float *e1, *e2, *op_, *bqkv;
    cudaGetSymbolAddress((void**)&p1h, g_p1h);
    cudaGetSymbolAddress((void**)&p1l, g_p1l);
    cudaGetSymbolAddress((void**)&p2h, g_p2h);
    cudaGetSymbolAddress((void**)&p2l, g_p2l);
    cudaGetSymbolAddress((void**)&hh, g_hh);
    cudaGetSymbolAddress((void**)&hl, g_hl);
    cudaGetSymbolAddress((void**)&oh, g_oh);
    cudaGetSymbolAddress((void**)&ol, g_ol);
    cudaGetSymbolAddress((void**)&qh, g_qkvh);
    cudaGetSymbolAddress((void**)&ql, g_qkvl);
    cudaGetSymbolAddress((void**)&w1h, g_w1h);
    cudaGetSymbolAddress((void**)&w1l, g_w1l);
    cudaGetSymbolAddress((void**)&w2h, g_w2h);
    cudaGetSymbolAddress((void**)&w2l, g_w2l);
    cudaGetSymbolAddress((void**)&wqh, g_wqh);
    cudaGetSymbolAddress((void**)&wql, g_wql);
    cudaGetSymbolAddress((void**)&wph, g_wph);
    cudaGetSymbolAddress((void**)&wpl, g_wpl);
    cudaGetSymbolAddress((void**)&e1, g_emb1);
    cudaGetSymbolAddress((void**)&e2, g_emb2);
    cudaGetSymbolAddress((void**)&op_, g_op);
    cudaGetSymbolAddress((void**)&bqkv, g_bqkv);

    cudaFuncSetAttribute(gemm_mma2, cudaFuncAttributeMaxDynamicSharedMemorySize, GEMM2_SMEM);
    cudaFuncSetAttribute(flash3_kernel, cudaFuncAttributeMaxDynamicSharedMemorySize, FA3_SMEM);

    im2row1_kernel<<<(ROWS_E * K1) / 256, 256>>>(x);
    im2row2_kernel<<<(ROWS_E * K2) / 256, 256>>>(x);
    wsplit_kernel<<<(256 * 768 + 255) / 256, 256>>>(W1, w1h, w1l, K1, EMBD);
    wsplit_kernel<<<(256 * 192 + 255) / 256, 256>>>(W2, w2h, w2l, K2, EMBD);
    wsplit_kernel<<<(256 * 256 + 255) / 256, 256>>>(Wp, wph, wpl, EMBD, EMBD);
    wqkv_split<<<(768 * 256) / 256, 256>>>(Wq, Wk, Wv, bq, bk, bv);

    // patch embeds -> fp32
    gemm_mma2<<<dim3(2, ROWS_E / 128), 256, GEMM2_SMEM>>>(p1h, p1l, w1h, w1l, nullptr, e1, nullptr, nullptr, ROWS_E, EMBD, K1);
    gemm_mma2<<<dim3(2, ROWS_E / 128), 256, GEMM2_SMEM>>>(p2h, p2l, w2h, w2l, nullptr, e2, nullptr, nullptr, ROWS_E, EMBD, K2);

    // fused assemble + LN1
    ln_fused_kernel<<<ROWS_T / 8, 256>>>(ln1g, ln1b, b1, cls1, b2, cls2);

    // fused QKV -> split bf16
    gemm_mma2<<<dim3(6, ROWS_T / 128), 256, GEMM2_SMEM>>>(hh, hl, wqh, wql, bqkv, nullptr, qh, ql, ROWS_T, 768, EMBD);

    // flash attention
    flash3_kernel<<<dim3(7, BATCH * HEADS), 128, FA3_SMEM>>>();

    // output projection -> fp32
    gemm_mma2<<<dim3(2, ROWS_T / 128), 256, GEMM2_SMEM>>>(oh, ol, wph, wpl, bp, op_, nullptr, nullptr, ROWS_T, EMBD, EMBD);

    ln_res_kernel<<<ROWS_T / 8, 256>>>(ln2g, ln2b);
    head_kernel<<<BATCH, 256>>>(lncg, lncb, Wc, bc, out);
}